// round 1
// baseline (speedup 1.0000x reference)
#include <cuda_runtime.h>

#define NU 100000
#define NP 200000
#define H  128
#define EV 500000
#define EL 150000

// ---------------- scratch layout (floats) ----------------
#define NPH 25600000LL   // NP*H
#define NUH 12800000LL   // NU*H
#define OFF_AGG_VP 0LL
#define OFF_AGG_LP 25600000LL
#define OFF_AGG_VU 51200000LL
#define OFF_AGG_LU 64000000LL
#define AGG_TOTAL  76800000LL
#define OFF_XU1    76800000LL
#define OFF_XP1    89600000LL
#define OFF_INV    115200000LL   // [cnt/inv VP(200k), LP(200k), VU(100k), LU(100k)]
#define OFF_B      115800000LL   // 4 * 384*128
#define OFF_BIAS   115996608LL   // 4 * 128
#define SCRATCH_FLOATS 115997120LL

__device__ __align__(256) float g_scratch[SCRATCH_FLOATS];

// ---------------- small helpers ----------------
__device__ __forceinline__ void red4(float* p, float4 v) {
    asm volatile("red.global.add.v4.f32 [%0], {%1,%2,%3,%4};"
                 :: "l"(p), "f"(v.x), "f"(v.y), "f"(v.z), "f"(v.w) : "memory");
}

__device__ __forceinline__ float2 u2f2(unsigned long long u) {
    float2 r;
    asm("mov.b64 {%0,%1}, %2;" : "=f"(r.x), "=f"(r.y) : "l"(u));
    return r;
}

// ---------------- counts ----------------
__global__ void count_edges(const int* __restrict__ src, const int* __restrict__ dst, int E,
                            float* __restrict__ cnt_srcside, float* __restrict__ cnt_dstside) {
    int i = blockIdx.x * blockDim.x + threadIdx.x;
    if (i < E) {
        atomicAdd(cnt_dstside + dst[i], 1.0f);
        atomicAdd(cnt_srcside + src[i], 1.0f);
    }
}

__global__ void invert_counts(float* __restrict__ p, int n) {
    int i = blockIdx.x * blockDim.x + threadIdx.x;
    if (i < n) {
        float c = p[i];
        p[i] = 1.0f / fmaxf(c, 1.0f);
    }
}

// ---------------- weight prep: Bcat[t][k(384)][n(128)], bias[t][n] ----------------
// t = layer*2 + isUser.  posts use rel {0,2}, users rel {1,3}.
__global__ void prep_B(const float* __restrict__ Wl, const float* __restrict__ bl,
                       const float* __restrict__ Wr,
                       float* __restrict__ Bcat, float* __restrict__ Bias) {
    int t = blockIdx.y;
    int idx = blockIdx.x * blockDim.x + threadIdx.x;   // 0..49151
    int layer = t >> 1, isU = t & 1;
    int rV = isU ? 1 : 0;
    int rL = rV + 2;
    int k = idx >> 7, n = idx & 127;
    const float* WlV = Wl + (size_t)((layer * 4 + rV) * 128) * 128;
    const float* WlL = Wl + (size_t)((layer * 4 + rL) * 128) * 128;
    const float* WrV = Wr + (size_t)((layer * 4 + rV) * 128) * 128;
    const float* WrL = Wr + (size_t)((layer * 4 + rL) * 128) * 128;
    float v;
    if (k < 128)       v = WlV[n * 128 + k];
    else if (k < 256)  v = WlL[n * 128 + (k - 128)];
    else               v = WrV[n * 128 + (k - 256)] + WrL[n * 128 + (k - 256)];
    Bcat[(size_t)t * 49152 + idx] = v;
    if (idx < 128)
        Bias[t * 128 + idx] = bl[(layer * 4 + rV) * 128 + idx] + bl[(layer * 4 + rL) * 128 + idx];
}

// ---------------- edge aggregation: one warp per edge, both directions ----------------
__global__ void edge_agg(const int* __restrict__ src, const int* __restrict__ dst, int E,
                         const float* __restrict__ xs, const float* __restrict__ xd,
                         float* __restrict__ agg_d, float* __restrict__ agg_s) {
    int w = (blockIdx.x * blockDim.x + threadIdx.x) >> 5;
    int lane = threadIdx.x & 31;
    if (w >= E) return;
    int s = src[w];
    int d = dst[w];
    float4 v1 = reinterpret_cast<const float4*>(xs)[(size_t)s * 32 + lane];
    red4(agg_d + (size_t)d * H + (lane << 2), v1);
    float4 v2 = reinterpret_cast<const float4*>(xd)[(size_t)d * 32 + lane];
    red4(agg_s + (size_t)s * H + (lane << 2), v2);
}

// ---------------- fused GEMM: out[M,128] = [A0*inv0 | A1*inv1 | A2] @ B(384x128) + bias ----------------
// BM=128, BN=128, BK=16, 256 threads, 8x8 per thread via packed fma.rn.f32x2 (pair over M).
template <bool RELU>
__global__ void __launch_bounds__(256, 2)
gemm384(const float* __restrict__ A0, const float* __restrict__ inv0,
        const float* __restrict__ A1, const float* __restrict__ inv1,
        const float* __restrict__ A2,
        const float* __restrict__ B, const float* __restrict__ bias,
        float* __restrict__ out, int M) {
    __shared__ float  As[16][132];       // [k][m], padded
    __shared__ float2 Bs[16][128];       // [k][n], value duplicated in both halves

    const int tid = threadIdx.x;
    const int tx = tid & 15;             // n group
    const int ty = tid >> 4;             // m group
    const int row0 = blockIdx.x << 7;

    unsigned long long acc[4][8];
#pragma unroll
    for (int i = 0; i < 4; ++i)
#pragma unroll
        for (int j = 0; j < 8; ++j) acc[i][j] = 0ULL;

#pragma unroll 1
    for (int kt = 0; kt < 24; ++kt) {
        const int seg = kt >> 3;
        const float* src  = (seg == 0) ? A0 : (seg == 1) ? A1 : A2;
        const float* invp = (seg == 0) ? inv0 : (seg == 1) ? inv1 : 0;
        const int kb = (kt & 7) << 4;

        // stage A tile (128 rows x 16 k), transposed + row-scaled
#pragma unroll
        for (int f0 = 0; f0 < 512; f0 += 256) {
            int f = f0 + tid;
            int m = f >> 2;
            int kq = (f & 3) << 2;
            int row = row0 + m;
            float4 v = make_float4(0.f, 0.f, 0.f, 0.f);
            float sc = 1.0f;
            if (row < M) {
                v = *reinterpret_cast<const float4*>(src + (size_t)row * H + kb + kq);
                if (invp) sc = invp[row];
            }
            As[kq + 0][m] = v.x * sc;
            As[kq + 1][m] = v.y * sc;
            As[kq + 2][m] = v.z * sc;
            As[kq + 3][m] = v.w * sc;
        }
        // stage B tile (16 k x 128 n), duplicated into f32x2 lanes
        const float* bsrc = B + (size_t)kt * 2048;
#pragma unroll
        for (int f0 = 0; f0 < 512; f0 += 256) {
            int f = f0 + tid;
            int kk = f >> 5;
            int n = (f & 31) << 2;
            float4 v = *reinterpret_cast<const float4*>(bsrc + kk * H + n);
            Bs[kk][n + 0] = make_float2(v.x, v.x);
            Bs[kk][n + 1] = make_float2(v.y, v.y);
            Bs[kk][n + 2] = make_float2(v.z, v.z);
            Bs[kk][n + 3] = make_float2(v.w, v.w);
        }
        __syncthreads();

#pragma unroll
        for (int kk = 0; kk < 16; ++kk) {
            const float* ap = &As[kk][ty << 3];
            ulonglong2 aA = *reinterpret_cast<const ulonglong2*>(ap);
            ulonglong2 aB = *reinterpret_cast<const ulonglong2*>(ap + 4);
            unsigned long long a[4] = {aA.x, aA.y, aB.x, aB.y};
            const ulonglong2* bp = reinterpret_cast<const ulonglong2*>(&Bs[kk][tx << 3]);
            ulonglong2 b01 = bp[0], b23 = bp[1], b45 = bp[2], b67 = bp[3];
            unsigned long long b[8] = {b01.x, b01.y, b23.x, b23.y, b45.x, b45.y, b67.x, b67.y};
#pragma unroll
            for (int i = 0; i < 4; ++i)
#pragma unroll
                for (int j = 0; j < 8; ++j)
                    asm("fma.rn.f32x2 %0, %1, %2, %0;" : "+l"(acc[i][j]) : "l"(a[i]), "l"(b[j]));
        }
        __syncthreads();
    }

    // epilogue
    float4 b03 = *reinterpret_cast<const float4*>(bias + (tx << 3));
    float4 b47 = *reinterpret_cast<const float4*>(bias + (tx << 3) + 4);
    float bv[8] = {b03.x, b03.y, b03.z, b03.w, b47.x, b47.y, b47.z, b47.w};

#pragma unroll
    for (int i = 0; i < 4; ++i) {
        int m0 = row0 + (ty << 3) + 2 * i;
        if (m0 >= M) break;
        float r0[8], r1[8];
#pragma unroll
        for (int j = 0; j < 8; ++j) {
            float2 p = u2f2(acc[i][j]);
            r0[j] = p.x + bv[j];
            r1[j] = p.y + bv[j];
            if (RELU) { r0[j] = fmaxf(r0[j], 0.f); r1[j] = fmaxf(r1[j], 0.f); }
        }
        float4* o0 = reinterpret_cast<float4*>(out + (size_t)m0 * H + (tx << 3));
        o0[0] = make_float4(r0[0], r0[1], r0[2], r0[3]);
        o0[1] = make_float4(r0[4], r0[5], r0[6], r0[7]);
        if (m0 + 1 < M) {
            float4* o1 = reinterpret_cast<float4*>(out + (size_t)(m0 + 1) * H + (tx << 3));
            o1[0] = make_float4(r1[0], r1[1], r1[2], r1[3]);
            o1[1] = make_float4(r1[4], r1[5], r1[6], r1[7]);
        }
    }
}

// ---------------- host ----------------
extern "C" void kernel_launch(void* const* d_in, const int* in_sizes, int n_in,
                              void* d_out, int out_size) {
    (void)in_sizes; (void)n_in; (void)out_size;
    const float* emb_u = (const float*)d_in[0];
    const float* emb_p = (const float*)d_in[1];
    const float* W_l   = (const float*)d_in[2];
    const float* b_l   = (const float*)d_in[3];
    const float* W_r   = (const float*)d_in[4];
    const int*   ev_s  = (const int*)d_in[5];
    const int*   ev_d  = (const int*)d_in[6];
    const int*   el_s  = (const int*)d_in[7];
    const int*   el_d  = (const int*)d_in[8];

    float* base = 0;
    cudaGetSymbolAddress((void**)&base, g_scratch);

    float* aggVP = base + OFF_AGG_VP;
    float* aggLP = base + OFF_AGG_LP;
    float* aggVU = base + OFF_AGG_VU;
    float* aggLU = base + OFF_AGG_LU;
    float* xu1   = base + OFF_XU1;
    float* xp1   = base + OFF_XP1;
    float* invVP = base + OFF_INV;
    float* invLP = invVP + NP;
    float* invVU = invLP + NP;
    float* invLU = invVU + NU;
    float* Bcat  = base + OFF_B;
    float* Bias  = base + OFF_BIAS;

    float* outU = (float*)d_out;
    float* outP = outU + (size_t)NU * H;

    const int NCNT = 2 * NP + 2 * NU;

    // counts + inverse degrees + fused weights (graph-independent of layer)
    cudaMemsetAsync(invVP, 0, (size_t)NCNT * sizeof(float));
    count_edges<<<(EV + 255) / 256, 256>>>(ev_s, ev_d, EV, invVU, invVP);
    count_edges<<<(EL + 255) / 256, 256>>>(el_s, el_d, EL, invLU, invLP);
    invert_counts<<<(NCNT + 255) / 256, 256>>>(invVP, NCNT);
    prep_B<<<dim3(192, 4), 256>>>(W_l, b_l, W_r, Bcat, Bias);

    for (int l = 0; l < 2; ++l) {
        cudaMemsetAsync(base, 0, (size_t)AGG_TOTAL * sizeof(float));
        const float* xu = l ? xu1 : emb_u;
        const float* xp = l ? xp1 : emb_p;
        edge_agg<<<(EV + 7) / 8, 256>>>(ev_s, ev_d, EV, xu, xp, aggVP, aggVU);
        edge_agg<<<(EL + 7) / 8, 256>>>(el_s, el_d, EL, xu, xp, aggLP, aggLU);

        float* op = l ? outP : xp1;
        float* ou = l ? outU : xu1;
        const float* Bp = Bcat + (size_t)(l * 2 + 0) * 49152;
        const float* Bu = Bcat + (size_t)(l * 2 + 1) * 49152;
        const float* bp_ = Bias + (l * 2 + 0) * 128;
        const float* bu_ = Bias + (l * 2 + 1) * 128;

        if (l == 0) {
            gemm384<true><<<(NP + 127) / 128, 256>>>(aggVP, invVP, aggLP, invLP, xp, Bp, bp_, op, NP);
            gemm384<true><<<(NU + 127) / 128, 256>>>(aggVU, invVU, aggLU, invLU, xu, Bu, bu_, ou, NU);
        } else {
            gemm384<false><<<(NP + 127) / 128, 256>>>(aggVP, invVP, aggLP, invLP, xp, Bp, bp_, op, NP);
            gemm384<false><<<(NU + 127) / 128, 256>>>(aggVU, invVU, aggLU, invLU, xu, Bu, bu_, ou, NU);
        }
    }
}

// round 2
// speedup vs baseline: 1.0002x; 1.0002x over previous
#include <cuda_runtime.h>

#define NU 100000
#define NP 200000
#define H  128
#define EV 500000
#define EL 150000

// ---------------- scratch layout (floats) ----------------
#define NPH 25600000LL   // NP*H
#define NUH 12800000LL   // NU*H
#define OFF_AGG_VP 0LL
#define OFF_AGG_LP 25600000LL
#define OFF_AGG_VU 51200000LL
#define OFF_AGG_LU 64000000LL
#define AGG_TOTAL  76800000LL
#define OFF_XU1    76800000LL
#define OFF_XP1    89600000LL
#define OFF_INV    115200000LL   // [cnt/inv VP(200k), LP(200k), VU(100k), LU(100k)]
#define OFF_B      115800000LL   // 4 * 384*128
#define OFF_BIAS   115996608LL   // 4 * 128
#define SCRATCH_FLOATS 115997120LL

__device__ __align__(256) float g_scratch[SCRATCH_FLOATS];

// ---------------- small helpers ----------------
__device__ __forceinline__ void red4(float* p, float4 v) {
    asm volatile("red.global.add.v4.f32 [%0], {%1,%2,%3,%4};"
                 :: "l"(p), "f"(v.x), "f"(v.y), "f"(v.z), "f"(v.w) : "memory");
}

__device__ __forceinline__ float2 u2f2(unsigned long long u) {
    float2 r;
    asm("mov.b64 {%0,%1}, %2;" : "=f"(r.x), "=f"(r.y) : "l"(u));
    return r;
}

// ---------------- counts ----------------
__global__ void count_edges(const int* __restrict__ src, const int* __restrict__ dst, int E,
                            float* __restrict__ cnt_srcside, float* __restrict__ cnt_dstside) {
    int i = blockIdx.x * blockDim.x + threadIdx.x;
    if (i < E) {
        atomicAdd(cnt_dstside + dst[i], 1.0f);
        atomicAdd(cnt_srcside + src[i], 1.0f);
    }
}

__global__ void invert_counts(float* __restrict__ p, int n) {
    int i = blockIdx.x * blockDim.x + threadIdx.x;
    if (i < n) {
        float c = p[i];
        p[i] = 1.0f / fmaxf(c, 1.0f);
    }
}

// ---------------- weight prep: Bcat[t][k(384)][n(128)], bias[t][n] ----------------
// t = layer*2 + isUser.  posts use rel {0,2}, users rel {1,3}.
__global__ void prep_B(const float* __restrict__ Wl, const float* __restrict__ bl,
                       const float* __restrict__ Wr,
                       float* __restrict__ Bcat, float* __restrict__ Bias) {
    int t = blockIdx.y;
    int idx = blockIdx.x * blockDim.x + threadIdx.x;   // 0..49151
    int layer = t >> 1, isU = t & 1;
    int rV = isU ? 1 : 0;
    int rL = rV + 2;
    int k = idx >> 7, n = idx & 127;
    const float* WlV = Wl + (size_t)((layer * 4 + rV) * 128) * 128;
    const float* WlL = Wl + (size_t)((layer * 4 + rL) * 128) * 128;
    const float* WrV = Wr + (size_t)((layer * 4 + rV) * 128) * 128;
    const float* WrL = Wr + (size_t)((layer * 4 + rL) * 128) * 128;
    float v;
    if (k < 128)       v = WlV[n * 128 + k];
    else if (k < 256)  v = WlL[n * 128 + (k - 128)];
    else               v = WrV[n * 128 + (k - 256)] + WrL[n * 128 + (k - 256)];
    Bcat[(size_t)t * 49152 + idx] = v;
    if (idx < 128)
        Bias[t * 128 + idx] = bl[(layer * 4 + rV) * 128 + idx] + bl[(layer * 4 + rL) * 128 + idx];
}

// ---------------- edge aggregation: one warp per edge, both directions ----------------
__global__ void edge_agg(const int* __restrict__ src, const int* __restrict__ dst, int E,
                         const float* __restrict__ xs, const float* __restrict__ xd,
                         float* __restrict__ agg_d, float* __restrict__ agg_s) {
    int w = (blockIdx.x * blockDim.x + threadIdx.x) >> 5;
    int lane = threadIdx.x & 31;
    if (w >= E) return;
    int s = src[w];
    int d = dst[w];
    float4 v1 = reinterpret_cast<const float4*>(xs)[(size_t)s * 32 + lane];
    red4(agg_d + (size_t)d * H + (lane << 2), v1);
    float4 v2 = reinterpret_cast<const float4*>(xd)[(size_t)d * 32 + lane];
    red4(agg_s + (size_t)s * H + (lane << 2), v2);
}

// ---------------- fused GEMM: out[M,128] = [A0*inv0 | A1*inv1 | A2] @ B(384x128) + bias ----------------
// BM=128, BN=128, BK=16, 256 threads, 8x8 per thread via packed fma.rn.f32x2 (pair over M).
template <bool RELU>
__global__ void __launch_bounds__(256, 2)
gemm384(const float* __restrict__ A0, const float* __restrict__ inv0,
        const float* __restrict__ A1, const float* __restrict__ inv1,
        const float* __restrict__ A2,
        const float* __restrict__ B, const float* __restrict__ bias,
        float* __restrict__ out, int M) {
    __shared__ float  As[16][132];       // [k][m], padded
    __shared__ float2 Bs[16][128];       // [k][n], value duplicated in both halves

    const int tid = threadIdx.x;
    const int tx = tid & 15;             // n group
    const int ty = tid >> 4;             // m group
    const int row0 = blockIdx.x << 7;

    unsigned long long acc[4][8];
#pragma unroll
    for (int i = 0; i < 4; ++i)
#pragma unroll
        for (int j = 0; j < 8; ++j) acc[i][j] = 0ULL;

#pragma unroll 1
    for (int kt = 0; kt < 24; ++kt) {
        const int seg = kt >> 3;
        const float* src  = (seg == 0) ? A0 : (seg == 1) ? A1 : A2;
        const float* invp = (seg == 0) ? inv0 : (seg == 1) ? inv1 : 0;
        const int kb = (kt & 7) << 4;

        // stage A tile (128 rows x 16 k), transposed + row-scaled
#pragma unroll
        for (int f0 = 0; f0 < 512; f0 += 256) {
            int f = f0 + tid;
            int m = f >> 2;
            int kq = (f & 3) << 2;
            int row = row0 + m;
            float4 v = make_float4(0.f, 0.f, 0.f, 0.f);
            float sc = 1.0f;
            if (row < M) {
                v = *reinterpret_cast<const float4*>(src + (size_t)row * H + kb + kq);
                if (invp) sc = invp[row];
            }
            As[kq + 0][m] = v.x * sc;
            As[kq + 1][m] = v.y * sc;
            As[kq + 2][m] = v.z * sc;
            As[kq + 3][m] = v.w * sc;
        }
        // stage B tile (16 k x 128 n), duplicated into f32x2 lanes
        const float* bsrc = B + (size_t)kt * 2048;
#pragma unroll
        for (int f0 = 0; f0 < 512; f0 += 256) {
            int f = f0 + tid;
            int kk = f >> 5;
            int n = (f & 31) << 2;
            float4 v = *reinterpret_cast<const float4*>(bsrc + kk * H + n);
            Bs[kk][n + 0] = make_float2(v.x, v.x);
            Bs[kk][n + 1] = make_float2(v.y, v.y);
            Bs[kk][n + 2] = make_float2(v.z, v.z);
            Bs[kk][n + 3] = make_float2(v.w, v.w);
        }
        __syncthreads();

#pragma unroll
        for (int kk = 0; kk < 16; ++kk) {
            const float* ap = &As[kk][ty << 3];
            ulonglong2 aA = *reinterpret_cast<const ulonglong2*>(ap);
            ulonglong2 aB = *reinterpret_cast<const ulonglong2*>(ap + 4);
            unsigned long long a[4] = {aA.x, aA.y, aB.x, aB.y};
            const ulonglong2* bp = reinterpret_cast<const ulonglong2*>(&Bs[kk][tx << 3]);
            ulonglong2 b01 = bp[0], b23 = bp[1], b45 = bp[2], b67 = bp[3];
            unsigned long long b[8] = {b01.x, b01.y, b23.x, b23.y, b45.x, b45.y, b67.x, b67.y};
#pragma unroll
            for (int i = 0; i < 4; ++i)
#pragma unroll
                for (int j = 0; j < 8; ++j)
                    asm("fma.rn.f32x2 %0, %1, %2, %0;" : "+l"(acc[i][j]) : "l"(a[i]), "l"(b[j]));
        }
        __syncthreads();
    }

    // epilogue
    float4 b03 = *reinterpret_cast<const float4*>(bias + (tx << 3));
    float4 b47 = *reinterpret_cast<const float4*>(bias + (tx << 3) + 4);
    float bv[8] = {b03.x, b03.y, b03.z, b03.w, b47.x, b47.y, b47.z, b47.w};

#pragma unroll
    for (int i = 0; i < 4; ++i) {
        int m0 = row0 + (ty << 3) + 2 * i;
        if (m0 >= M) break;
        float r0[8], r1[8];
#pragma unroll
        for (int j = 0; j < 8; ++j) {
            float2 p = u2f2(acc[i][j]);
            r0[j] = p.x + bv[j];
            r1[j] = p.y + bv[j];
            if (RELU) { r0[j] = fmaxf(r0[j], 0.f); r1[j] = fmaxf(r1[j], 0.f); }
        }
        float4* o0 = reinterpret_cast<float4*>(out + (size_t)m0 * H + (tx << 3));
        o0[0] = make_float4(r0[0], r0[1], r0[2], r0[3]);
        o0[1] = make_float4(r0[4], r0[5], r0[6], r0[7]);
        if (m0 + 1 < M) {
            float4* o1 = reinterpret_cast<float4*>(out + (size_t)(m0 + 1) * H + (tx << 3));
            o1[0] = make_float4(r1[0], r1[1], r1[2], r1[3]);
            o1[1] = make_float4(r1[4], r1[5], r1[6], r1[7]);
        }
    }
}

// ---------------- host ----------------
extern "C" void kernel_launch(void* const* d_in, const int* in_sizes, int n_in,
                              void* d_out, int out_size) {
    (void)in_sizes; (void)n_in; (void)out_size;
    const float* emb_u = (const float*)d_in[0];
    const float* emb_p = (const float*)d_in[1];
    const float* W_l   = (const float*)d_in[2];
    const float* b_l   = (const float*)d_in[3];
    const float* W_r   = (const float*)d_in[4];
    const int*   ev_s  = (const int*)d_in[5];
    const int*   ev_d  = (const int*)d_in[6];
    const int*   el_s  = (const int*)d_in[7];
    const int*   el_d  = (const int*)d_in[8];

    float* base = 0;
    cudaGetSymbolAddress((void**)&base, g_scratch);

    float* aggVP = base + OFF_AGG_VP;
    float* aggLP = base + OFF_AGG_LP;
    float* aggVU = base + OFF_AGG_VU;
    float* aggLU = base + OFF_AGG_LU;
    float* xu1   = base + OFF_XU1;
    float* xp1   = base + OFF_XP1;
    float* invVP = base + OFF_INV;
    float* invLP = invVP + NP;
    float* invVU = invLP + NP;
    float* invLU = invVU + NU;
    float* Bcat  = base + OFF_B;
    float* Bias  = base + OFF_BIAS;

    float* outU = (float*)d_out;
    float* outP = outU + (size_t)NU * H;

    const int NCNT = 2 * NP + 2 * NU;

    // counts + inverse degrees + fused weights (graph-independent of layer)
    cudaMemsetAsync(invVP, 0, (size_t)NCNT * sizeof(float));
    count_edges<<<(EV + 255) / 256, 256>>>(ev_s, ev_d, EV, invVU, invVP);
    count_edges<<<(EL + 255) / 256, 256>>>(el_s, el_d, EL, invLU, invLP);
    invert_counts<<<(NCNT + 255) / 256, 256>>>(invVP, NCNT);
    prep_B<<<dim3(192, 4), 256>>>(W_l, b_l, W_r, Bcat, Bias);

    for (int l = 0; l < 2; ++l) {
        cudaMemsetAsync(base, 0, (size_t)AGG_TOTAL * sizeof(float));
        const float* xu = l ? xu1 : emb_u;
        const float* xp = l ? xp1 : emb_p;
        edge_agg<<<(EV + 7) / 8, 256>>>(ev_s, ev_d, EV, xu, xp, aggVP, aggVU);
        edge_agg<<<(EL + 7) / 8, 256>>>(el_s, el_d, EL, xu, xp, aggLP, aggLU);

        float* op = l ? outP : xp1;
        float* ou = l ? outU : xu1;
        const float* Bp = Bcat + (size_t)(l * 2 + 0) * 49152;
        const float* Bu = Bcat + (size_t)(l * 2 + 1) * 49152;
        const float* bp_ = Bias + (l * 2 + 0) * 128;
        const float* bu_ = Bias + (l * 2 + 1) * 128;

        if (l == 0) {
            gemm384<true><<<(NP + 127) / 128, 256>>>(aggVP, invVP, aggLP, invLP, xp, Bp, bp_, op, NP);
            gemm384<true><<<(NU + 127) / 128, 256>>>(aggVU, invVU, aggLU, invLU, xu, Bu, bu_, ou, NU);
        } else {
            gemm384<false><<<(NP + 127) / 128, 256>>>(aggVP, invVP, aggLP, invLP, xp, Bp, bp_, op, NP);
            gemm384<false><<<(NU + 127) / 128, 256>>>(aggVU, invVU, aggLU, invLU, xu, Bu, bu_, ou, NU);
        }
    }
}

// round 4
// speedup vs baseline: 3.4682x; 3.4676x over previous
#include <cuda_runtime.h>
#include <cuda_bf16.h>
#include <cstdint>

#define NU 100000
#define NP 200000
#define H  128
#define EV 500000
#define EL 150000
#define NALL (2*NP + 2*NU)        // 600000

// ---------------- scratch layout (4-byte units) ----------------
#define OFF_AGG_VP 0LL
#define OFF_AGG_LP 25600000LL
#define OFF_AGG_VU 51200000LL
#define OFF_AGG_LU 64000000LL
#define OFF_XU1    76800000LL
#define OFF_XP1    89600000LL
#define OFF_INT    115200000LL
#define OFF_BH     118400000LL    // 4*49152 bf16 = 98304 floats
#define OFF_BL     118498304LL
#define OFF_BIAS   118596608LL
#define SCRATCH_FLOATS 118600000LL

// int offsets inside int region (region is 3.2M ints)
#define I_CNT  0
#define I_OFFS 600064            // NALL+1 entries
#define I_CUR  1200192
#define I_BSUM 1800192
#define I_POOL 1801600           // 2*(EV+EL) = 1300000

__device__ __align__(1024) float g_scratch[SCRATCH_FLOATS];

// ---------------- PTX helpers (base-target only: sm_80-class) ----------------
__device__ __forceinline__ uint32_t smem_u32(const void* p) {
    uint32_t a;
    asm("{ .reg .u64 t; cvta.to.shared.u64 t, %1; cvt.u32.u64 %0, t; }" : "=r"(a) : "l"(p));
    return a;
}
__device__ __forceinline__ void ldsm_x4(uint32_t& r0, uint32_t& r1, uint32_t& r2, uint32_t& r3,
                                        uint32_t addr) {
    asm volatile("ldmatrix.sync.aligned.m8n8.x4.shared.b16 {%0,%1,%2,%3}, [%4];"
                 : "=r"(r0), "=r"(r1), "=r"(r2), "=r"(r3) : "r"(addr));
}
__device__ __forceinline__ void mma_bf16(float* d, const uint32_t* a, const uint32_t* b) {
    asm volatile("mma.sync.aligned.m16n8k16.row.col.f32.bf16.bf16.f32 "
                 "{%0,%1,%2,%3}, {%4,%5,%6,%7}, {%8,%9}, {%0,%1,%2,%3};"
                 : "+f"(d[0]), "+f"(d[1]), "+f"(d[2]), "+f"(d[3])
                 : "r"(a[0]), "r"(a[1]), "r"(a[2]), "r"(a[3]), "r"(b[0]), "r"(b[1]));
}

// ---------------- CSR build ----------------
__global__ void k_hist(const int* __restrict__ vs, const int* __restrict__ vd,
                       const int* __restrict__ ls, const int* __restrict__ ld,
                       int* __restrict__ cnt) {
    int i = blockIdx.x * blockDim.x + threadIdx.x;
    if (i < EV) { atomicAdd(&cnt[vd[i]], 1); atomicAdd(&cnt[2*NP + vs[i]], 1); }
    if (i < EL) { atomicAdd(&cnt[NP + ld[i]], 1); atomicAdd(&cnt[2*NP + NU + ls[i]], 1); }
}

__global__ void k_scan1(const int* __restrict__ in, int* __restrict__ out,
                        int* __restrict__ bsum, int n) {
    __shared__ int sh[1024];
    int t = threadIdx.x, g = blockIdx.x * 1024 + t;
    int v = (g < n) ? in[g] : 0;
    sh[t] = v; __syncthreads();
    for (int off = 1; off < 1024; off <<= 1) {
        int x = (t >= off) ? sh[t - off] : 0;
        __syncthreads();
        sh[t] += x;
        __syncthreads();
    }
    if (g < n) out[g] = sh[t] - v;
    if (t == 1023) bsum[blockIdx.x] = sh[t];
}
__global__ void k_scan2(int* __restrict__ bsum, int nb, int* __restrict__ offs, int n) {
    __shared__ int sh[1024];
    int t = threadIdx.x;
    int v = (t < nb) ? bsum[t] : 0;
    sh[t] = v; __syncthreads();
    for (int off = 1; off < 1024; off <<= 1) {
        int x = (t >= off) ? sh[t - off] : 0;
        __syncthreads();
        sh[t] += x;
        __syncthreads();
    }
    if (t < nb) bsum[t] = sh[t] - v;
    if (t == 1023) offs[n] = sh[t];
}
__global__ void k_scan3(int* __restrict__ out, const int* __restrict__ bsum, int n) {
    int g = blockIdx.x * 1024 + threadIdx.x;
    if (g < n) out[g] += bsum[blockIdx.x];
}

__global__ void k_scatter(const int* __restrict__ vs, const int* __restrict__ vd,
                          const int* __restrict__ ls, const int* __restrict__ ld,
                          int* __restrict__ cur, int* __restrict__ pool) {
    int i = blockIdx.x * blockDim.x + threadIdx.x;
    if (i < EV) {
        int p = atomicAdd(&cur[vd[i]], 1);             pool[p] = vs[i];
        int q = atomicAdd(&cur[2*NP + vs[i]], 1);      pool[q] = vd[i];
    }
    if (i < EL) {
        int p = atomicAdd(&cur[NP + ld[i]], 1);        pool[p] = ls[i];
        int q = atomicAdd(&cur[2*NP + NU + ls[i]], 1); pool[q] = ld[i];
    }
}

// ---------------- CSR mean aggregation: one warp per node-slot ----------------
__global__ void agg_csr(const int* __restrict__ offs, const int* __restrict__ pool,
                        const float* __restrict__ xu, const float* __restrict__ xp,
                        float* __restrict__ aVP, float* __restrict__ aLP,
                        float* __restrict__ aVU, float* __restrict__ aLU) {
    int w = (blockIdx.x * blockDim.x + threadIdx.x) >> 5;
    int lane = threadIdx.x & 31;
    if (w >= NALL) return;
    const float* X; float* out;
    if (w < NP)                { X = xu; out = aVP + (size_t)w * H; }
    else if (w < 2*NP)         { X = xu; out = aLP + (size_t)(w - NP) * H; }
    else if (w < 2*NP + NU)    { X = xp; out = aVU + (size_t)(w - 2*NP) * H; }
    else                       { X = xp; out = aLU + (size_t)(w - 2*NP - NU) * H; }
    int beg = offs[w], end = offs[w + 1];
    float4 acc = make_float4(0.f, 0.f, 0.f, 0.f);
    for (int i = beg; i < end; ++i) {
        int idx = __ldg(pool + i);
        float4 v = __ldg(reinterpret_cast<const float4*>(X) + (size_t)idx * 32 + lane);
        acc.x += v.x; acc.y += v.y; acc.z += v.z; acc.w += v.w;
    }
    float inv = 1.0f / fmaxf((float)(end - beg), 1.0f);
    acc.x *= inv; acc.y *= inv; acc.z *= inv; acc.w *= inv;
    reinterpret_cast<float4*>(out)[lane] = acc;
}

// ---------------- weight prep: B[t][n(128)][k(384)] split into bf16 hi/lo ----------------
__global__ void prep_B(const float* __restrict__ Wl, const float* __restrict__ bl,
                       const float* __restrict__ Wr,
                       __nv_bfloat16* __restrict__ Bh, __nv_bfloat16* __restrict__ Blo,
                       float* __restrict__ Bias) {
    int t = blockIdx.y;
    int idx = blockIdx.x * blockDim.x + threadIdx.x;   // < 49152
    int layer = t >> 1, isU = t & 1;
    int rV = isU ? 1 : 0, rL = rV + 2;
    int n = idx / 384, k = idx % 384;
    const float* WlV = Wl + (size_t)((layer * 4 + rV) * 128) * 128;
    const float* WlL = Wl + (size_t)((layer * 4 + rL) * 128) * 128;
    const float* WrV = Wr + (size_t)((layer * 4 + rV) * 128) * 128;
    const float* WrL = Wr + (size_t)((layer * 4 + rL) * 128) * 128;
    float v;
    if (k < 128)      v = WlV[n * 128 + k];
    else if (k < 256) v = WlL[n * 128 + (k - 128)];
    else              v = WrV[n * 128 + (k - 256)] + WrL[n * 128 + (k - 256)];
    __nv_bfloat16 h = __float2bfloat16(v);
    Bh[(size_t)t * 49152 + idx]  = h;
    Blo[(size_t)t * 49152 + idx] = __float2bfloat16(v - __bfloat162float(h));
    if (idx < 128)
        Bias[t * 128 + idx] = bl[(layer * 4 + rV) * 128 + idx] + bl[(layer * 4 + rL) * 128 + idx];
}

// ---------------- mma.sync bf16-split GEMM ----------------
// out[M,128] = [A0 | A1 | A2](M x 384 fp32) @ B^T + bias; B stored [n][k].
// Block: 128x128 tile, 256 thr (8 warps: wm=warp&3 over M, wn=warp>>2 over N).
// K chunks of 64 staged to SMEM as bf16 hi/lo, rows padded to 72 (144B: ldmatrix conflict-free).
#define RSTR 72
#define GSMEM (4 * 128 * RSTR * 2)    // 73728 B

template <bool RELU>
__global__ void __launch_bounds__(256, 1)
gemm_mma(const float* __restrict__ A0, const float* __restrict__ A1,
         const float* __restrict__ A2,
         const __nv_bfloat16* __restrict__ Bh, const __nv_bfloat16* __restrict__ Bl,
         const float* __restrict__ bias, float* __restrict__ out, int M) {
    extern __shared__ __align__(16) __nv_bfloat16 sm[];
    __nv_bfloat16* sAh = sm;
    __nv_bfloat16* sAl = sAh + 128 * RSTR;
    __nv_bfloat16* sBh = sAl + 128 * RSTR;
    __nv_bfloat16* sBl = sBh + 128 * RSTR;
    const uint32_t uAh = smem_u32(sAh), uAl = smem_u32(sAl);
    const uint32_t uBh = smem_u32(sBh), uBl = smem_u32(sBl);

    const int tid = threadIdx.x;
    const int warp = tid >> 5, lane = tid & 31;
    const int wm = warp & 3, wn = warp >> 2;
    const int row0 = blockIdx.x << 7;

    float acc[2][8][4];
#pragma unroll
    for (int i = 0; i < 2; ++i)
#pragma unroll
        for (int j = 0; j < 8; ++j)
#pragma unroll
            for (int q = 0; q < 4; ++q) acc[i][j][q] = 0.f;

    // staging indices
    const int sr = tid >> 1;               // 0..127 row
    const int sh = (tid & 1) << 5;         // k-half 0/32
    const uint32_t soff = sr * RSTR + sh;  // element offset

    // ldmatrix addresses (element offsets computed per use)
    const int lA_row = lane & 15, lA_k = (lane >> 4) << 3;
    const int lB_row = ((lane >> 4) & 1) * 8 + (lane & 7);
    const int lB_k = ((lane >> 3) & 1) << 3;

#pragma unroll 1
    for (int c = 0; c < 6; ++c) {
        // ---- stage A chunk (128 x 64 fp32 -> bf16 hi/lo) ----
        {
            const float* Asrc = (c < 2) ? A0 : (c < 4) ? A1 : A2;
            const int kb = (c & 1) << 6;
            const int row = row0 + sr;
            const bool ok = row < M;
            const float4* ap = reinterpret_cast<const float4*>(Asrc + (size_t)row * H + kb + sh);
#pragma unroll
            for (int q = 0; q < 8; ++q) {
                float4 v = ok ? __ldg(ap + q) : make_float4(0.f, 0.f, 0.f, 0.f);
                __nv_bfloat162 h01 = __floats2bfloat162_rn(v.x, v.y);
                __nv_bfloat162 h23 = __floats2bfloat162_rn(v.z, v.w);
                float2 f01 = __bfloat1622float2(h01);
                float2 f23 = __bfloat1622float2(h23);
                __nv_bfloat162 l01 = __floats2bfloat162_rn(v.x - f01.x, v.y - f01.y);
                __nv_bfloat162 l23 = __floats2bfloat162_rn(v.z - f23.x, v.w - f23.y);
                uint2 uh, ul;
                uh.x = *reinterpret_cast<uint32_t*>(&h01); uh.y = *reinterpret_cast<uint32_t*>(&h23);
                ul.x = *reinterpret_cast<uint32_t*>(&l01); ul.y = *reinterpret_cast<uint32_t*>(&l23);
                *reinterpret_cast<uint2*>(sAh + soff + q * 4) = uh;
                *reinterpret_cast<uint2*>(sAl + soff + q * 4) = ul;
            }
        }
        // ---- stage B chunk (128 n-rows x 64 bf16 hi/lo) ----
        {
            const __nv_bfloat16* bhp = Bh + (size_t)sr * 384 + c * 64 + sh;
            const __nv_bfloat16* blp = Bl + (size_t)sr * 384 + c * 64 + sh;
#pragma unroll
            for (int q = 0; q < 4; ++q) {
                uint4 vh = __ldg(reinterpret_cast<const uint4*>(bhp) + q);
                uint4 vl = __ldg(reinterpret_cast<const uint4*>(blp) + q);
                *(reinterpret_cast<uint4*>(sBh + soff) + q) = vh;
                *(reinterpret_cast<uint4*>(sBl + soff) + q) = vl;
            }
        }
        __syncthreads();

        // ---- compute 4 k-steps of 16 ----
#pragma unroll
        for (int ks = 0; ks < 4; ++ks) {
            uint32_t ah[2][4], al[2][4];
#pragma unroll
            for (int mt = 0; mt < 2; ++mt) {
                uint32_t eo = ((wm * 32 + mt * 16 + lA_row) * RSTR + ks * 16 + lA_k) * 2;
                ldsm_x4(ah[mt][0], ah[mt][1], ah[mt][2], ah[mt][3], uAh + eo);
                ldsm_x4(al[mt][0], al[mt][1], al[mt][2], al[mt][3], uAl + eo);
            }
            uint32_t bh2[4][4], bl2[4][4];
#pragma unroll
            for (int np = 0; np < 4; ++np) {
                uint32_t eo = ((wn * 64 + np * 16 + lB_row) * RSTR + ks * 16 + lB_k) * 2;
                ldsm_x4(bh2[np][0], bh2[np][1], bh2[np][2], bh2[np][3], uBh + eo);
                ldsm_x4(bl2[np][0], bl2[np][1], bl2[np][2], bl2[np][3], uBl + eo);
            }
#pragma unroll
            for (int mt = 0; mt < 2; ++mt)
#pragma unroll
                for (int nt = 0; nt < 8; ++nt) {
                    const uint32_t* bhp = &bh2[nt >> 1][(nt & 1) << 1];
                    const uint32_t* blp = &bl2[nt >> 1][(nt & 1) << 1];
                    mma_bf16(acc[mt][nt], ah[mt], bhp);   // hh
                    mma_bf16(acc[mt][nt], ah[mt], blp);   // h*l
                    mma_bf16(acc[mt][nt], al[mt], bhp);   // l*h
                }
        }
        __syncthreads();
    }

    // ---- epilogue ----
    const int lr = lane >> 2;
    const int lc = (lane & 3) << 1;
#pragma unroll
    for (int mt = 0; mt < 2; ++mt) {
        int r0 = row0 + wm * 32 + mt * 16 + lr;
#pragma unroll
        for (int nt = 0; nt < 8; ++nt) {
            int cn = wn * 64 + nt * 8 + lc;
            float b0 = __ldg(bias + cn), b1 = __ldg(bias + cn + 1);
            float* a4 = acc[mt][nt];
            if (r0 < M) {
                float2 o = make_float2(a4[0] + b0, a4[1] + b1);
                if (RELU) { o.x = fmaxf(o.x, 0.f); o.y = fmaxf(o.y, 0.f); }
                *reinterpret_cast<float2*>(out + (size_t)r0 * H + cn) = o;
            }
            if (r0 + 8 < M) {
                float2 o = make_float2(a4[2] + b0, a4[3] + b1);
                if (RELU) { o.x = fmaxf(o.x, 0.f); o.y = fmaxf(o.y, 0.f); }
                *reinterpret_cast<float2*>(out + (size_t)(r0 + 8) * H + cn) = o;
            }
        }
    }
}

// ---------------- host ----------------
extern "C" void kernel_launch(void* const* d_in, const int* in_sizes, int n_in,
                              void* d_out, int out_size) {
    (void)in_sizes; (void)n_in; (void)out_size;
    const float* emb_u = (const float*)d_in[0];
    const float* emb_p = (const float*)d_in[1];
    const float* W_l   = (const float*)d_in[2];
    const float* b_l   = (const float*)d_in[3];
    const float* W_r   = (const float*)d_in[4];
    const int*   ev_s  = (const int*)d_in[5];
    const int*   ev_d  = (const int*)d_in[6];
    const int*   el_s  = (const int*)d_in[7];
    const int*   el_d  = (const int*)d_in[8];

    float* base = 0;
    cudaGetSymbolAddress((void**)&base, g_scratch);

    float* aVP = base + OFF_AGG_VP;
    float* aLP = base + OFF_AGG_LP;
    float* aVU = base + OFF_AGG_VU;
    float* aLU = base + OFF_AGG_LU;
    float* xu1 = base + OFF_XU1;
    float* xp1 = base + OFF_XP1;
    int*   ip  = (int*)(base + OFF_INT);
    int* cnt  = ip + I_CNT;
    int* offs = ip + I_OFFS;
    int* cur  = ip + I_CUR;
    int* bsum = ip + I_BSUM;
    int* pool = ip + I_POOL;
    __nv_bfloat16* Bh = (__nv_bfloat16*)(base + OFF_BH);
    __nv_bfloat16* Bl = (__nv_bfloat16*)(base + OFF_BL);
    float* Bias = base + OFF_BIAS;

    float* outU = (float*)d_out;
    float* outP = outU + (size_t)NU * H;

    cudaFuncSetAttribute(gemm_mma<true>,  cudaFuncAttributeMaxDynamicSharedMemorySize, GSMEM);
    cudaFuncSetAttribute(gemm_mma<false>, cudaFuncAttributeMaxDynamicSharedMemorySize, GSMEM);

    // ---- CSR build (once; reused by both layers) ----
    cudaMemsetAsync(cnt, 0, (size_t)NALL * sizeof(int));
    k_hist<<<(EV + 255) / 256, 256>>>(ev_s, ev_d, el_s, el_d, cnt);
    const int nb = (NALL + 1023) / 1024;   // 586
    k_scan1<<<nb, 1024>>>(cnt, offs, bsum, NALL);
    k_scan2<<<1, 1024>>>(bsum, nb, offs, NALL);
    k_scan3<<<nb, 1024>>>(offs, bsum, NALL);
    cudaMemcpyAsync(cur, offs, (size_t)NALL * sizeof(int), cudaMemcpyDeviceToDevice);
    k_scatter<<<(EV + 255) / 256, 256>>>(ev_s, ev_d, el_s, el_d, cur, pool);
    prep_B<<<dim3(192, 4), 256>>>(W_l, b_l, W_r, Bh, Bl, Bias);

    const int AGG_BLOCKS = NALL / 8;   // 8 warps/block, exact
    const int GP = (NP + 127) / 128, GU = (NU + 127) / 128;

    // ---- layer 0 ----
    agg_csr<<<AGG_BLOCKS, 256>>>(offs, pool, emb_u, emb_p, aVP, aLP, aVU, aLU);
    gemm_mma<true><<<GP, 256, GSMEM>>>(aVP, aLP, emb_p, Bh + 0 * 49152, Bl + 0 * 49152,
                                       Bias + 0 * 128, xp1, NP);
    gemm_mma<true><<<GU, 256, GSMEM>>>(aVU, aLU, emb_u, Bh + 1 * 49152, Bl + 1 * 49152,
                                       Bias + 1 * 128, xu1, NU);
    // ---- layer 1 ----
    agg_csr<<<AGG_BLOCKS, 256>>>(offs, pool, xu1, xp1, aVP, aLP, aVU, aLU);
    gemm_mma<false><<<GP, 256, GSMEM>>>(aVP, aLP, xp1, Bh + 2 * 49152, Bl + 2 * 49152,
                                        Bias + 2 * 128, outP, NP);
    gemm_mma<false><<<GU, 256, GSMEM>>>(aVU, aLU, xu1, Bh + 3 * 49152, Bl + 3 * 49152,
                                        Bias + 3 * 128, outU, NU);
}

// round 6
// speedup vs baseline: 3.7276x; 1.0748x over previous
#include <cuda_runtime.h>
#include <cuda_fp16.h>
#include <cstdint>

#define NU 100000
#define NP 200000
#define H  128
#define EV 500000
#define EL 150000
#define NALL (2*NP + 2*NU)        // 600000

// ---------------- scratch layout (4-byte units) ----------------
#define OFF_AGG_VP 0LL
#define OFF_AGG_LP 25600000LL
#define OFF_AGG_VU 51200000LL
#define OFF_AGG_LU 64000000LL
#define OFF_XU1    76800000LL
#define OFF_XP1    89600000LL
#define OFF_INT    115200000LL
#define OFF_BH     118400000LL    // 4*49152 fp16 = 98304 floats of space
#define OFF_BIAS   118498304LL
#define SCRATCH_FLOATS 118500000LL

// int offsets inside int region
#define I_CNT  0
#define I_TOT  600000            // 64-pad
#define I_OFFS 600064
#define I_CUR  1200128
#define I_POOL 1800192           // 2*(EV+EL) = 1300000

__device__ __align__(1024) float g_scratch[SCRATCH_FLOATS];

// ---------------- PTX helpers (base-target safe) ----------------
__device__ __forceinline__ uint32_t smem_u32(const void* p) {
    uint32_t a;
    asm("{ .reg .u64 t; cvta.to.shared.u64 t, %1; cvt.u32.u64 %0, t; }" : "=r"(a) : "l"(p));
    return a;
}
__device__ __forceinline__ void ldsm_x4(uint32_t& r0, uint32_t& r1, uint32_t& r2, uint32_t& r3,
                                        uint32_t addr) {
    asm volatile("ldmatrix.sync.aligned.m8n8.x4.shared.b16 {%0,%1,%2,%3}, [%4];"
                 : "=r"(r0), "=r"(r1), "=r"(r2), "=r"(r3) : "r"(addr));
}
__device__ __forceinline__ void mma_f16(float* d, const uint32_t* a, const uint32_t* b) {
    asm volatile("mma.sync.aligned.m16n8k16.row.col.f32.f16.f16.f32 "
                 "{%0,%1,%2,%3}, {%4,%5,%6,%7}, {%8,%9}, {%0,%1,%2,%3};"
                 : "+f"(d[0]), "+f"(d[1]), "+f"(d[2]), "+f"(d[3])
                 : "r"(a[0]), "r"(a[1]), "r"(a[2]), "r"(a[3]), "r"(b[0]), "r"(b[1]));
}

// ---------------- CSR build (unordered ticket allocation) ----------------
__global__ void k_hist(const int* __restrict__ vs, const int* __restrict__ vd,
                       const int* __restrict__ ls, const int* __restrict__ ld,
                       int* __restrict__ cnt) {
    int i = blockIdx.x * blockDim.x + threadIdx.x;
    if (i < EV) { atomicAdd(&cnt[vd[i]], 1); atomicAdd(&cnt[2*NP + vs[i]], 1); }
    if (i < EL) { atomicAdd(&cnt[NP + ld[i]], 1); atomicAdd(&cnt[2*NP + NU + ls[i]], 1); }
}

__global__ void k_alloc(const int* __restrict__ cnt, int* __restrict__ offs,
                        int* __restrict__ cur, int* __restrict__ tot) {
    int w = blockIdx.x * blockDim.x + threadIdx.x;
    if (w >= NALL) return;
    int c = cnt[w];
    int base = c ? atomicAdd(tot, c) : 0;
    offs[w] = base;
    cur[w] = base;
}

__global__ void k_scatter(const int* __restrict__ vs, const int* __restrict__ vd,
                          const int* __restrict__ ls, const int* __restrict__ ld,
                          int* __restrict__ cur, int* __restrict__ pool) {
    int i = blockIdx.x * blockDim.x + threadIdx.x;
    if (i < EV) {
        int p = atomicAdd(&cur[vd[i]], 1);             pool[p] = vs[i];
        int q = atomicAdd(&cur[2*NP + vs[i]], 1);      pool[q] = vd[i];
    }
    if (i < EL) {
        int p = atomicAdd(&cur[NP + ld[i]], 1);        pool[p] = ls[i];
        int q = atomicAdd(&cur[2*NP + NU + ls[i]], 1); pool[q] = ld[i];
    }
}

// ---------------- CSR mean aggregation: one warp per node-slot, MLP=2 ----------------
__global__ void agg_csr(const int* __restrict__ offs, const int* __restrict__ cnt,
                        const int* __restrict__ pool,
                        const float* __restrict__ xu, const float* __restrict__ xp,
                        float* __restrict__ aVP, float* __restrict__ aLP,
                        float* __restrict__ aVU, float* __restrict__ aLU) {
    int w = (blockIdx.x * blockDim.x + threadIdx.x) >> 5;
    int lane = threadIdx.x & 31;
    if (w >= NALL) return;
    const float* X; float* out;
    if (w < NP)                { X = xu; out = aVP + (size_t)w * H; }
    else if (w < 2*NP)         { X = xu; out = aLP + (size_t)(w - NP) * H; }
    else if (w < 2*NP + NU)    { X = xp; out = aVU + (size_t)(w - 2*NP) * H; }
    else                       { X = xp; out = aLU + (size_t)(w - 2*NP - NU) * H; }
    int beg = offs[w];
    int deg = cnt[w];
    int end = beg + deg;
    float4 acc0 = make_float4(0.f, 0.f, 0.f, 0.f);
    float4 acc1 = make_float4(0.f, 0.f, 0.f, 0.f);
    int i = beg;
    for (; i + 1 < end; i += 2) {
        int i0 = __ldg(pool + i);
        int i1 = __ldg(pool + i + 1);
        float4 v0 = __ldg(reinterpret_cast<const float4*>(X) + (size_t)i0 * 32 + lane);
        float4 v1 = __ldg(reinterpret_cast<const float4*>(X) + (size_t)i1 * 32 + lane);
        acc0.x += v0.x; acc0.y += v0.y; acc0.z += v0.z; acc0.w += v0.w;
        acc1.x += v1.x; acc1.y += v1.y; acc1.z += v1.z; acc1.w += v1.w;
    }
    if (i < end) {
        int i0 = __ldg(pool + i);
        float4 v0 = __ldg(reinterpret_cast<const float4*>(X) + (size_t)i0 * 32 + lane);
        acc0.x += v0.x; acc0.y += v0.y; acc0.z += v0.z; acc0.w += v0.w;
    }
    float inv = 1.0f / fmaxf((float)deg, 1.0f);
    float4 r;
    r.x = (acc0.x + acc1.x) * inv;
    r.y = (acc0.y + acc1.y) * inv;
    r.z = (acc0.z + acc1.z) * inv;
    r.w = (acc0.w + acc1.w) * inv;
    reinterpret_cast<float4*>(out)[lane] = r;
}

// ---------------- weight prep: B[t][n(128)][k(384)] as fp16 ----------------
__global__ void prep_B(const float* __restrict__ Wl, const float* __restrict__ bl,
                       const float* __restrict__ Wr,
                       __half* __restrict__ Bh, float* __restrict__ Bias) {
    int t = blockIdx.y;
    int idx = blockIdx.x * blockDim.x + threadIdx.x;   // < 49152
    int layer = t >> 1, isU = t & 1;
    int rV = isU ? 1 : 0, rL = rV + 2;
    int n = idx / 384, k = idx % 384;
    const float* WlV = Wl + (size_t)((layer * 4 + rV) * 128) * 128;
    const float* WlL = Wl + (size_t)((layer * 4 + rL) * 128) * 128;
    const float* WrV = Wr + (size_t)((layer * 4 + rV) * 128) * 128;
    const float* WrL = Wr + (size_t)((layer * 4 + rL) * 128) * 128;
    float v;
    if (k < 128)      v = WlV[n * 128 + k];
    else if (k < 256) v = WlL[n * 128 + (k - 128)];
    else              v = WrV[n * 128 + (k - 256)] + WrL[n * 128 + (k - 256)];
    Bh[(size_t)t * 49152 + idx] = __float2half_rn(v);
    if (idx < 128)
        Bias[t * 128 + idx] = bl[(layer * 4 + rV) * 128 + idx] + bl[(layer * 4 + rL) * 128 + idx];
}

// ---------------- mma.sync fp16 2-pass GEMM ----------------
// out[M,128] = [A0|A1|A2](M x 384 fp32) @ B^T + bias; B fp16 [n][k]; A = Ah + Al in fp16.
#define RSTR 72
#define GSMEM (3 * 128 * RSTR * 2)    // 55296 B

template <bool RELU>
__global__ void __launch_bounds__(256)
gemm_mma(const float* __restrict__ A0, const float* __restrict__ A1,
         const float* __restrict__ A2,
         const __half* __restrict__ Bh,
         const float* __restrict__ bias, float* __restrict__ out, int M) {
    extern __shared__ __align__(16) __half sm[];
    __half* sAh = sm;
    __half* sAl = sAh + 128 * RSTR;
    __half* sB  = sAl + 128 * RSTR;
    const uint32_t uAh = smem_u32(sAh), uAl = smem_u32(sAl), uB = smem_u32(sB);

    const int tid = threadIdx.x;
    const int warp = tid >> 5, lane = tid & 31;
    const int wm = warp & 3, wn = warp >> 2;
    const int row0 = blockIdx.x << 7;

    float acc[2][8][4];
#pragma unroll
    for (int i = 0; i < 2; ++i)
#pragma unroll
        for (int j = 0; j < 8; ++j)
#pragma unroll
            for (int q = 0; q < 4; ++q) acc[i][j][q] = 0.f;

    const int sr = tid >> 1;               // staging row 0..127
    const int shf = (tid & 1) << 5;        // k-half 0/32
    const uint32_t soff = sr * RSTR + shf;

    const int lA_row = lane & 15, lA_k = (lane >> 4) << 3;
    const int lB_row = ((lane >> 4) & 1) * 8 + (lane & 7);
    const int lB_k = ((lane >> 3) & 1) << 3;

#pragma unroll 1
    for (int c = 0; c < 6; ++c) {
        // ---- stage A chunk (128 x 64 fp32 -> fp16 hi/lo, 32 halves per thread) ----
        {
            const float* Asrc = (c < 2) ? A0 : (c < 4) ? A1 : A2;
            const int kb = (c & 1) << 6;
            const int row = row0 + sr;
            const bool ok = row < M;
            const float4* ap = reinterpret_cast<const float4*>(Asrc + (size_t)row * H + kb + shf);
#pragma unroll
            for (int q = 0; q < 8; ++q) {
                float4 v = ok ? __ldg(ap + q) : make_float4(0.f, 0.f, 0.f, 0.f);
                __half2 h01 = __floats2half2_rn(v.x, v.y);
                __half2 h23 = __floats2half2_rn(v.z, v.w);
                float2 f01 = __half22float2(h01);
                float2 f23 = __half22float2(h23);
                __half2 l01 = __floats2half2_rn(v.x - f01.x, v.y - f01.y);
                __half2 l23 = __floats2half2_rn(v.z - f23.x, v.w - f23.y);
                uint2 uh, ul;
                uh.x = *reinterpret_cast<uint32_t*>(&h01); uh.y = *reinterpret_cast<uint32_t*>(&h23);
                ul.x = *reinterpret_cast<uint32_t*>(&l01); ul.y = *reinterpret_cast<uint32_t*>(&l23);
                *reinterpret_cast<uint2*>(sAh + soff + q * 4) = uh;
                *reinterpret_cast<uint2*>(sAl + soff + q * 4) = ul;
            }
        }
        // ---- stage B chunk (128 n-rows x 64 fp16): 4 x uint4 = 32 halves per thread ----
        {
            const __half* bp = Bh + (size_t)sr * 384 + c * 64 + shf;
#pragma unroll
            for (int q = 0; q < 4; ++q) {
                uint4 v = __ldg(reinterpret_cast<const uint4*>(bp) + q);
                *(reinterpret_cast<uint4*>(sB + soff) + q) = v;
            }
        }
        __syncthreads();

        // ---- compute 4 k-steps of 16 ----
#pragma unroll
        for (int ks = 0; ks < 4; ++ks) {
            uint32_t ah[2][4], al[2][4];
#pragma unroll
            for (int mt = 0; mt < 2; ++mt) {
                uint32_t eo = ((wm * 32 + mt * 16 + lA_row) * RSTR + ks * 16 + lA_k) * 2;
                ldsm_x4(ah[mt][0], ah[mt][1], ah[mt][2], ah[mt][3], uAh + eo);
                ldsm_x4(al[mt][0], al[mt][1], al[mt][2], al[mt][3], uAl + eo);
            }
            uint32_t bf[4][4];
#pragma unroll
            for (int np = 0; np < 4; ++np) {
                uint32_t eo = ((wn * 64 + np * 16 + lB_row) * RSTR + ks * 16 + lB_k) * 2;
                ldsm_x4(bf[np][0], bf[np][1], bf[np][2], bf[np][3], uB + eo);
            }
#pragma unroll
            for (int mt = 0; mt < 2; ++mt)
#pragma unroll
                for (int nt = 0; nt < 8; ++nt) {
                    const uint32_t* bp = &bf[nt >> 1][(nt & 1) << 1];
                    mma_f16(acc[mt][nt], ah[mt], bp);   // A_hi * B
                    mma_f16(acc[mt][nt], al[mt], bp);   // A_lo * B
                }
        }
        __syncthreads();
    }

    // ---- epilogue ----
    const int lr = lane >> 2;
    const int lc = (lane & 3) << 1;
#pragma unroll
    for (int mt = 0; mt < 2; ++mt) {
        int r0 = row0 + wm * 32 + mt * 16 + lr;
#pragma unroll
        for (int nt = 0; nt < 8; ++nt) {
            int cn = wn * 64 + nt * 8 + lc;
            float b0 = __ldg(bias + cn), b1 = __ldg(bias + cn + 1);
            float* a4 = acc[mt][nt];
            if (r0 < M) {
                float2 o = make_float2(a4[0] + b0, a4[1] + b1);
                if (RELU) { o.x = fmaxf(o.x, 0.f); o.y = fmaxf(o.y, 0.f); }
                *reinterpret_cast<float2*>(out + (size_t)r0 * H + cn) = o;
            }
            if (r0 + 8 < M) {
                float2 o = make_float2(a4[2] + b0, a4[3] + b1);
                if (RELU) { o.x = fmaxf(o.x, 0.f); o.y = fmaxf(o.y, 0.f); }
                *reinterpret_cast<float2*>(out + (size_t)(r0 + 8) * H + cn) = o;
            }
        }
    }
}

// ---------------- host ----------------
extern "C" void kernel_launch(void* const* d_in, const int* in_sizes, int n_in,
                              void* d_out, int out_size) {
    (void)in_sizes; (void)n_in; (void)out_size;
    const float* emb_u = (const float*)d_in[0];
    const float* emb_p = (const float*)d_in[1];
    const float* W_l   = (const float*)d_in[2];
    const float* b_l   = (const float*)d_in[3];
    const float* W_r   = (const float*)d_in[4];
    const int*   ev_s  = (const int*)d_in[5];
    const int*   ev_d  = (const int*)d_in[6];
    const int*   el_s  = (const int*)d_in[7];
    const int*   el_d  = (const int*)d_in[8];

    float* base = 0;
    cudaGetSymbolAddress((void**)&base, g_scratch);

    float* aVP = base + OFF_AGG_VP;
    float* aLP = base + OFF_AGG_LP;
    float* aVU = base + OFF_AGG_VU;
    float* aLU = base + OFF_AGG_LU;
    float* xu1 = base + OFF_XU1;
    float* xp1 = base + OFF_XP1;
    int*   ip  = (int*)(base + OFF_INT);
    int* cnt  = ip + I_CNT;
    int* tot  = ip + I_TOT;
    int* offs = ip + I_OFFS;
    int* cur  = ip + I_CUR;
    int* pool = ip + I_POOL;
    __half* Bh = (__half*)(base + OFF_BH);
    float* Bias = base + OFF_BIAS;

    float* outU = (float*)d_out;
    float* outP = outU + (size_t)NU * H;

    cudaFuncSetAttribute(gemm_mma<true>,  cudaFuncAttributeMaxDynamicSharedMemorySize, GSMEM);
    cudaFuncSetAttribute(gemm_mma<false>, cudaFuncAttributeMaxDynamicSharedMemorySize, GSMEM);

    // ---- CSR build (once; reused by both layers) ----
    cudaMemsetAsync(cnt, 0, (size_t)(NALL + 64) * sizeof(int));   // cnt + tot
    k_hist<<<(EV + 255) / 256, 256>>>(ev_s, ev_d, el_s, el_d, cnt);
    k_alloc<<<(NALL + 255) / 256, 256>>>(cnt, offs, cur, tot);
    k_scatter<<<(EV + 255) / 256, 256>>>(ev_s, ev_d, el_s, el_d, cur, pool);
    prep_B<<<dim3(192, 4), 256>>>(W_l, b_l, W_r, Bh, Bias);

    const int AGG_BLOCKS = NALL / 8;   // 8 warps/block, exact
    const int GP = (NP + 127) / 128, GU = (NU + 127) / 128;

    // ---- layer 0 ----
    agg_csr<<<AGG_BLOCKS, 256>>>(offs, cnt, pool, emb_u, emb_p, aVP, aLP, aVU, aLU);
    gemm_mma<true><<<GP, 256, GSMEM>>>(aVP, aLP, emb_p, Bh + 0 * 49152,
                                       Bias + 0 * 128, xp1, NP);
    gemm_mma<true><<<GU, 256, GSMEM>>>(aVU, aLU, emb_u, Bh + 1 * 49152,
                                       Bias + 1 * 128, xu1, NU);
    // ---- layer 1 ----
    agg_csr<<<AGG_BLOCKS, 256>>>(offs, cnt, pool, xu1, xp1, aVP, aLP, aVU, aLU);
    gemm_mma<false><<<GP, 256, GSMEM>>>(aVP, aLP, xp1, Bh + 2 * 49152,
                                        Bias + 2 * 128, outP, NP);
    gemm_mma<false><<<GU, 256, GSMEM>>>(aVU, aLU, xu1, Bh + 3 * 49152,
                                        Bias + 3 * 128, outU, NU);
}

// round 7
// speedup vs baseline: 5.0137x; 1.3450x over previous
#include <cuda_runtime.h>
#include <cuda_fp16.h>
#include <cstdint>

#define NU 100000
#define NP 200000
#define H  128
#define EV 500000
#define EL 150000
#define NALL (2*NP + 2*NU)        // 600000

// ---------------- scratch layout (4-byte float units) ----------------
#define OFF_AVP 0LL               // NP x 128 fp16  = 12.8M floats
#define OFF_ALP 12800000LL
#define OFF_AVU 25600000LL        // NU x 128 fp16  = 6.4M
#define OFF_ALU 32000000LL
#define OFF_XU0 38400000LL        // emb_u fp16
#define OFF_XP0 44800000LL        // emb_p fp16
#define OFF_XU1 57600000LL        // layer-0 user out fp16
#define OFF_XP1 64000000LL        // layer-0 post out fp16
#define OFF_INT 76800000LL
#define OFF_BH  80000000LL        // 4*49152 fp16
#define OFF_BIAS 80098304LL
#define SCRATCH_FLOATS 80100000LL

// int offsets inside int region
#define I_CNT  0
#define I_TOT  600000
#define I_OFFS 600064
#define I_CUR  1200128
#define I_POOL 1800192            // 1.3M entries

__device__ __align__(1024) float g_scratch[SCRATCH_FLOATS];

// ---------------- PTX helpers (base-target safe) ----------------
__device__ __forceinline__ uint32_t smem_u32(const void* p) {
    uint32_t a;
    asm("{ .reg .u64 t; cvta.to.shared.u64 t, %1; cvt.u32.u64 %0, t; }" : "=r"(a) : "l"(p));
    return a;
}
__device__ __forceinline__ void ldsm_x4(uint32_t& r0, uint32_t& r1, uint32_t& r2, uint32_t& r3,
                                        uint32_t addr) {
    asm volatile("ldmatrix.sync.aligned.m8n8.x4.shared.b16 {%0,%1,%2,%3}, [%4];"
                 : "=r"(r0), "=r"(r1), "=r"(r2), "=r"(r3) : "r"(addr));
}
__device__ __forceinline__ void mma_f16(float* d, const uint32_t* a, const uint32_t* b) {
    asm volatile("mma.sync.aligned.m16n8k16.row.col.f32.f16.f16.f32 "
                 "{%0,%1,%2,%3}, {%4,%5,%6,%7}, {%8,%9}, {%0,%1,%2,%3};"
                 : "+f"(d[0]), "+f"(d[1]), "+f"(d[2]), "+f"(d[3])
                 : "r"(a[0]), "r"(a[1]), "r"(a[2]), "r"(a[3]), "r"(b[0]), "r"(b[1]));
}

// ---------------- CSR build ----------------
__global__ void k_hist(const int* __restrict__ vs, const int* __restrict__ vd,
                       const int* __restrict__ ls, const int* __restrict__ ld,
                       int* __restrict__ cnt) {
    int i = blockIdx.x * blockDim.x + threadIdx.x;
    if (i < EV) { atomicAdd(&cnt[vd[i]], 1); atomicAdd(&cnt[2*NP + vs[i]], 1); }
    if (i < EL) { atomicAdd(&cnt[NP + ld[i]], 1); atomicAdd(&cnt[2*NP + NU + ls[i]], 1); }
}

__global__ void k_alloc(const int* __restrict__ cnt, int* __restrict__ offs,
                        int* __restrict__ cur, int* __restrict__ tot) {
    int w = blockIdx.x * blockDim.x + threadIdx.x;
    if (w >= NALL) return;
    int c = cnt[w];
    int base = c ? atomicAdd(tot, c) : 0;
    offs[w] = base;
    cur[w] = base;
}

__global__ void k_scatter(const int* __restrict__ vs, const int* __restrict__ vd,
                          const int* __restrict__ ls, const int* __restrict__ ld,
                          int* __restrict__ cur, int* __restrict__ pool) {
    int i = blockIdx.x * blockDim.x + threadIdx.x;
    if (i < EV) {
        int p = atomicAdd(&cur[vd[i]], 1);             pool[p] = vs[i];
        int q = atomicAdd(&cur[2*NP + vs[i]], 1);      pool[q] = vd[i];
    }
    if (i < EL) {
        int p = atomicAdd(&cur[NP + ld[i]], 1);        pool[p] = ls[i];
        int q = atomicAdd(&cur[2*NP + NU + ls[i]], 1); pool[q] = ld[i];
    }
}

// ---------------- fused prep: B fp16 + bias, and emb fp32 -> fp16 tables ----------------
#define CVT_GROUPS ((NU + NP) * 16)           // groups of 8 halves
#define CVT_BLOCKS ((CVT_GROUPS + 255) / 256) // 18750
__global__ void k_prep(const float* __restrict__ Wl, const float* __restrict__ bl,
                       const float* __restrict__ Wr,
                       const float* __restrict__ eu, const float* __restrict__ ep,
                       __half* __restrict__ Bh, float* __restrict__ Bias,
                       __half* __restrict__ xu16, __half* __restrict__ xp16) {
    int b = blockIdx.x;
    if (b < 768) {
        int t = b / 192;
        int idx = (b % 192) * 256 + threadIdx.x;   // < 49152
        int layer = t >> 1, isU = t & 1;
        int rV = isU ? 1 : 0, rL = rV + 2;
        int n = idx / 384, k = idx % 384;
        const float* WlV = Wl + (size_t)((layer * 4 + rV) * 128) * 128;
        const float* WlL = Wl + (size_t)((layer * 4 + rL) * 128) * 128;
        const float* WrV = Wr + (size_t)((layer * 4 + rV) * 128) * 128;
        const float* WrL = Wr + (size_t)((layer * 4 + rL) * 128) * 128;
        float v;
        if (k < 128)      v = WlV[n * 128 + k];
        else if (k < 256) v = WlL[n * 128 + (k - 128)];
        else              v = WrV[n * 128 + (k - 256)] + WrL[n * 128 + (k - 256)];
        Bh[(size_t)t * 49152 + idx] = __float2half_rn(v);
        if (idx < 128)
            Bias[t * 128 + idx] = bl[(layer * 4 + rV) * 128 + idx] + bl[(layer * 4 + rL) * 128 + idx];
    } else {
        long i = (long)(b - 768) * 256 + threadIdx.x;
        if (i >= CVT_GROUPS) return;
        const float* src; __half* dst; long j;
        if (i < (long)NU * 16) { src = eu; dst = xu16; j = i; }
        else                   { src = ep; dst = xp16; j = i - (long)NU * 16; }
        float4 a = __ldg(reinterpret_cast<const float4*>(src) + j * 2);
        float4 c = __ldg(reinterpret_cast<const float4*>(src) + j * 2 + 1);
        __half2 h0 = __floats2half2_rn(a.x, a.y);
        __half2 h1 = __floats2half2_rn(a.z, a.w);
        __half2 h2 = __floats2half2_rn(c.x, c.y);
        __half2 h3 = __floats2half2_rn(c.z, c.w);
        uint4 o;
        o.x = *reinterpret_cast<uint32_t*>(&h0);
        o.y = *reinterpret_cast<uint32_t*>(&h1);
        o.z = *reinterpret_cast<uint32_t*>(&h2);
        o.w = *reinterpret_cast<uint32_t*>(&h3);
        reinterpret_cast<uint4*>(dst)[j] = o;
    }
}

// ---------------- CSR mean aggregation (fp16 tables, fp32 accum, fp16 out) ----------------
__global__ void agg_csr(const int* __restrict__ offs, const int* __restrict__ cnt,
                        const int* __restrict__ pool,
                        const __half* __restrict__ xu, const __half* __restrict__ xp,
                        __half* __restrict__ aVP, __half* __restrict__ aLP,
                        __half* __restrict__ aVU, __half* __restrict__ aLU) {
    int w = (blockIdx.x * blockDim.x + threadIdx.x) >> 5;
    int lane = threadIdx.x & 31;
    if (w >= NALL) return;
    const __half* X; __half* out;
    if (w < NP)                { X = xu; out = aVP + (size_t)w * H; }
    else if (w < 2*NP)         { X = xu; out = aLP + (size_t)(w - NP) * H; }
    else if (w < 2*NP + NU)    { X = xp; out = aVU + (size_t)(w - 2*NP) * H; }
    else                       { X = xp; out = aLU + (size_t)(w - 2*NP - NU) * H; }
    int beg = offs[w];
    int deg = cnt[w];
    int end = beg + deg;
    float4 acc0 = make_float4(0.f, 0.f, 0.f, 0.f);
    float4 acc1 = make_float4(0.f, 0.f, 0.f, 0.f);
    int i = beg;
    for (; i + 1 < end; i += 2) {
        int i0 = __ldg(pool + i);
        int i1 = __ldg(pool + i + 1);
        uint2 v0 = __ldg(reinterpret_cast<const uint2*>(X + (size_t)i0 * H) + lane);
        uint2 v1 = __ldg(reinterpret_cast<const uint2*>(X + (size_t)i1 * H) + lane);
        float2 a = __half22float2(*reinterpret_cast<__half2*>(&v0.x));
        float2 b = __half22float2(*reinterpret_cast<__half2*>(&v0.y));
        acc0.x += a.x; acc0.y += a.y; acc0.z += b.x; acc0.w += b.y;
        float2 c = __half22float2(*reinterpret_cast<__half2*>(&v1.x));
        float2 d = __half22float2(*reinterpret_cast<__half2*>(&v1.y));
        acc1.x += c.x; acc1.y += c.y; acc1.z += d.x; acc1.w += d.y;
    }
    if (i < end) {
        int i0 = __ldg(pool + i);
        uint2 v0 = __ldg(reinterpret_cast<const uint2*>(X + (size_t)i0 * H) + lane);
        float2 a = __half22float2(*reinterpret_cast<__half2*>(&v0.x));
        float2 b = __half22float2(*reinterpret_cast<__half2*>(&v0.y));
        acc0.x += a.x; acc0.y += a.y; acc0.z += b.x; acc0.w += b.y;
    }
    float inv = 1.0f / fmaxf((float)deg, 1.0f);
    __half2 r01 = __floats2half2_rn((acc0.x + acc1.x) * inv, (acc0.y + acc1.y) * inv);
    __half2 r23 = __floats2half2_rn((acc0.z + acc1.z) * inv, (acc0.w + acc1.w) * inv);
    uint2 o;
    o.x = *reinterpret_cast<uint32_t*>(&r01);
    o.y = *reinterpret_cast<uint32_t*>(&r23);
    reinterpret_cast<uint2*>(out)[lane] = o;
}

// ---------------- mma.sync fp16 single-pass GEMM ----------------
// out[M,128] = [A0|A1|A2](M x 384 fp16) @ B^T + bias; all operands fp16, fp32 accum.
#define RSTR 72
#define GSMEM (2 * 128 * RSTR * 2)    // 36864 B

template <bool OUTH>   // true: fp16 out + relu (layer 0); false: fp32 out (layer 1)
__global__ void __launch_bounds__(256)
gemm_mma(const __half* __restrict__ A0, const __half* __restrict__ A1,
         const __half* __restrict__ A2,
         const __half* __restrict__ Bh,
         const float* __restrict__ bias, void* __restrict__ outv, int M) {
    extern __shared__ __align__(16) __half sm[];
    __half* sA = sm;
    __half* sB = sA + 128 * RSTR;
    const uint32_t uA = smem_u32(sA), uB = smem_u32(sB);

    const int tid = threadIdx.x;
    const int warp = tid >> 5, lane = tid & 31;
    const int wm = warp & 3, wn = warp >> 2;
    const int row0 = blockIdx.x << 7;

    float acc[2][8][4];
#pragma unroll
    for (int i = 0; i < 2; ++i)
#pragma unroll
        for (int j = 0; j < 8; ++j)
#pragma unroll
            for (int q = 0; q < 4; ++q) acc[i][j][q] = 0.f;

    const int sr = tid >> 1;               // staging row 0..127
    const int shf = (tid & 1) << 5;        // k-half 0/32 (halves)
    const uint32_t soff = sr * RSTR + shf;

    const int lA_row = lane & 15, lA_k = (lane >> 4) << 3;
    const int lB_row = ((lane >> 4) & 1) * 8 + (lane & 7);
    const int lB_k = ((lane >> 3) & 1) << 3;

#pragma unroll 1
    for (int c = 0; c < 6; ++c) {
        // ---- stage A chunk: 128 rows x 64 halves (pure copy) ----
        {
            const __half* Asrc = (c < 2) ? A0 : (c < 4) ? A1 : A2;
            const int kb = (c & 1) << 6;
            const int row = row0 + sr;
            const bool ok = row < M;
            const uint4* ap = reinterpret_cast<const uint4*>(Asrc + (size_t)row * H + kb + shf);
            const uint4 z = make_uint4(0, 0, 0, 0);
#pragma unroll
            for (int q = 0; q < 4; ++q) {
                uint4 v = ok ? __ldg(ap + q) : z;
                *(reinterpret_cast<uint4*>(sA + soff) + q) = v;
            }
        }
        // ---- stage B chunk: 128 n-rows x 64 halves ----
        {
            const __half* bp = Bh + (size_t)sr * 384 + c * 64 + shf;
#pragma unroll
            for (int q = 0; q < 4; ++q) {
                uint4 v = __ldg(reinterpret_cast<const uint4*>(bp) + q);
                *(reinterpret_cast<uint4*>(sB + soff) + q) = v;
            }
        }
        __syncthreads();

        // ---- compute 4 k-steps of 16 ----
#pragma unroll
        for (int ks = 0; ks < 4; ++ks) {
            uint32_t af[2][4];
#pragma unroll
            for (int mt = 0; mt < 2; ++mt) {
                uint32_t eo = ((wm * 32 + mt * 16 + lA_row) * RSTR + ks * 16 + lA_k) * 2;
                ldsm_x4(af[mt][0], af[mt][1], af[mt][2], af[mt][3], uA + eo);
            }
            uint32_t bf[4][4];
#pragma unroll
            for (int np = 0; np < 4; ++np) {
                uint32_t eo = ((wn * 64 + np * 16 + lB_row) * RSTR + ks * 16 + lB_k) * 2;
                ldsm_x4(bf[np][0], bf[np][1], bf[np][2], bf[np][3], uB + eo);
            }
#pragma unroll
            for (int mt = 0; mt < 2; ++mt)
#pragma unroll
                for (int nt = 0; nt < 8; ++nt)
                    mma_f16(acc[mt][nt], af[mt], &bf[nt >> 1][(nt & 1) << 1]);
        }
        __syncthreads();
    }

    // ---- epilogue ----
    const int lr = lane >> 2;
    const int lc = (lane & 3) << 1;
#pragma unroll
    for (int mt = 0; mt < 2; ++mt) {
        int r0 = row0 + wm * 32 + mt * 16 + lr;
#pragma unroll
        for (int nt = 0; nt < 8; ++nt) {
            int cn = wn * 64 + nt * 8 + lc;
            float b0 = __ldg(bias + cn), b1 = __ldg(bias + cn + 1);
            float* a4 = acc[mt][nt];
            if (OUTH) {
                __half* o16 = (__half*)outv;
                if (r0 < M) {
                    __half2 h = __floats2half2_rn(fmaxf(a4[0] + b0, 0.f), fmaxf(a4[1] + b1, 0.f));
                    *reinterpret_cast<__half2*>(o16 + (size_t)r0 * H + cn) = h;
                }
                if (r0 + 8 < M) {
                    __half2 h = __floats2half2_rn(fmaxf(a4[2] + b0, 0.f), fmaxf(a4[3] + b1, 0.f));
                    *reinterpret_cast<__half2*>(o16 + (size_t)(r0 + 8) * H + cn) = h;
                }
            } else {
                float* o32 = (float*)outv;
                if (r0 < M)
                    *reinterpret_cast<float2*>(o32 + (size_t)r0 * H + cn) =
                        make_float2(a4[0] + b0, a4[1] + b1);
                if (r0 + 8 < M)
                    *reinterpret_cast<float2*>(o32 + (size_t)(r0 + 8) * H + cn) =
                        make_float2(a4[2] + b0, a4[3] + b1);
            }
        }
    }
}

// ---------------- host ----------------
extern "C" void kernel_launch(void* const* d_in, const int* in_sizes, int n_in,
                              void* d_out, int out_size) {
    (void)in_sizes; (void)n_in; (void)out_size;
    const float* emb_u = (const float*)d_in[0];
    const float* emb_p = (const float*)d_in[1];
    const float* W_l   = (const float*)d_in[2];
    const float* b_l   = (const float*)d_in[3];
    const float* W_r   = (const float*)d_in[4];
    const int*   ev_s  = (const int*)d_in[5];
    const int*   ev_d  = (const int*)d_in[6];
    const int*   el_s  = (const int*)d_in[7];
    const int*   el_d  = (const int*)d_in[8];

    float* base = 0;
    cudaGetSymbolAddress((void**)&base, g_scratch);

    __half* aVP  = (__half*)(base + OFF_AVP);
    __half* aLP  = (__half*)(base + OFF_ALP);
    __half* aVU  = (__half*)(base + OFF_AVU);
    __half* aLU  = (__half*)(base + OFF_ALU);
    __half* xu0  = (__half*)(base + OFF_XU0);
    __half* xp0  = (__half*)(base + OFF_XP0);
    __half* xu1  = (__half*)(base + OFF_XU1);
    __half* xp1  = (__half*)(base + OFF_XP1);
    int*   ip  = (int*)(base + OFF_INT);
    int* cnt  = ip + I_CNT;
    int* tot  = ip + I_TOT;
    int* offs = ip + I_OFFS;
    int* cur  = ip + I_CUR;
    int* pool = ip + I_POOL;
    __half* Bh = (__half*)(base + OFF_BH);
    float* Bias = base + OFF_BIAS;

    float* outU = (float*)d_out;
    float* outP = outU + (size_t)NU * H;

    cudaFuncSetAttribute(gemm_mma<true>,  cudaFuncAttributeMaxDynamicSharedMemorySize, GSMEM);
    cudaFuncSetAttribute(gemm_mma<false>, cudaFuncAttributeMaxDynamicSharedMemorySize, GSMEM);

    // ---- CSR build + prep (launch order puts agg_csr in the profiled slot) ----
    cudaMemsetAsync(cnt, 0, (size_t)(NALL + 64) * sizeof(int));
    k_hist<<<(EV + 255) / 256, 256>>>(ev_s, ev_d, el_s, el_d, cnt);
    k_alloc<<<(NALL + 255) / 256, 256>>>(cnt, offs, cur, tot);
    k_scatter<<<(EV + 255) / 256, 256>>>(ev_s, ev_d, el_s, el_d, cur, pool);
    k_prep<<<768 + CVT_BLOCKS, 256>>>(W_l, b_l, W_r, emb_u, emb_p, Bh, Bias, xu0, xp0);

    const int AGG_BLOCKS = NALL / 8;
    const int GP = (NP + 127) / 128, GU = (NU + 127) / 128;

    // ---- layer 0 ----
    agg_csr<<<AGG_BLOCKS, 256>>>(offs, cnt, pool, xu0, xp0, aVP, aLP, aVU, aLU);
    gemm_mma<true><<<GP, 256, GSMEM>>>(aVP, aLP, xp0, Bh + 0 * 49152,
                                       Bias + 0 * 128, xp1, NP);
    gemm_mma<true><<<GU, 256, GSMEM>>>(aVU, aLU, xu0, Bh + 1 * 49152,
                                       Bias + 1 * 128, xu1, NU);
    // ---- layer 1 ----
    agg_csr<<<AGG_BLOCKS, 256>>>(offs, cnt, pool, xu1, xp1, aVP, aLP, aVU, aLU);
    gemm_mma<false><<<GP, 256, GSMEM>>>(aVP, aLP, xp1, Bh + 2 * 49152,
                                        Bias + 2 * 128, outP, NP);
    gemm_mma<false><<<GU, 256, GSMEM>>>(aVU, aLU, xu1, Bh + 3 * 49152,
                                        Bias + 3 * 128, outU, NU);
}

// round 8
// speedup vs baseline: 5.3221x; 1.0615x over previous
#include <cuda_runtime.h>
#include <cuda_fp16.h>
#include <cstdint>

#define NU 100000
#define NP 200000
#define H  128
#define EV 500000
#define EL 150000
#define NALL (2*NP + 2*NU)        // 600000
#define GP 1563                   // ceil(NP/128)
#define GU 782                    // ceil(NU/128)

// ---------------- scratch layout (4-byte float units) ----------------
#define OFF_AVP 0LL               // NP x 128 fp16
#define OFF_ALP 12800000LL
#define OFF_AVU 25600000LL        // NU x 128 fp16
#define OFF_ALU 32000000LL
#define OFF_XU0 38400000LL        // emb_u fp16
#define OFF_XP0 44800000LL        // emb_p fp16
#define OFF_XU1 57600000LL        // layer-0 user out fp16
#define OFF_XP1 64000000LL        // layer-0 post out fp16
#define OFF_INT 76800000LL
#define OFF_BH  80000000LL        // 4*49152 fp16
#define OFF_BIAS 80098304LL
#define SCRATCH_FLOATS 80100000LL

// int offsets inside int region
#define I_CNT  0
#define I_TOT  600000
#define I_OFFS 600064
#define I_CUR  1200128
#define I_POOL 1800192            // 1.3M entries

__device__ __align__(1024) float g_scratch[SCRATCH_FLOATS];

// ---------------- PTX helpers (base-target safe, sm_80-class) ----------------
__device__ __forceinline__ uint32_t smem_u32(const void* p) {
    uint32_t a;
    asm("{ .reg .u64 t; cvta.to.shared.u64 t, %1; cvt.u32.u64 %0, t; }" : "=r"(a) : "l"(p));
    return a;
}
__device__ __forceinline__ void ldsm_x4(uint32_t& r0, uint32_t& r1, uint32_t& r2, uint32_t& r3,
                                        uint32_t addr) {
    asm volatile("ldmatrix.sync.aligned.m8n8.x4.shared.b16 {%0,%1,%2,%3}, [%4];"
                 : "=r"(r0), "=r"(r1), "=r"(r2), "=r"(r3) : "r"(addr));
}
__device__ __forceinline__ void mma_f16(float* d, const uint32_t* a, const uint32_t* b) {
    asm volatile("mma.sync.aligned.m16n8k16.row.col.f32.f16.f16.f32 "
                 "{%0,%1,%2,%3}, {%4,%5,%6,%7}, {%8,%9}, {%0,%1,%2,%3};"
                 : "+f"(d[0]), "+f"(d[1]), "+f"(d[2]), "+f"(d[3])
                 : "r"(a[0]), "r"(a[1]), "r"(a[2]), "r"(a[3]), "r"(b[0]), "r"(b[1]));
}
__device__ __forceinline__ void cp16(uint32_t dst, const void* src, int sz) {
    asm volatile("cp.async.cg.shared.global [%0], [%1], 16, %2;"
                 :: "r"(dst), "l"(src), "r"(sz) : "memory");
}
#define CP_COMMIT() asm volatile("cp.async.commit_group;" ::: "memory")
#define CP_WAIT1()  asm volatile("cp.async.wait_group 1;" ::: "memory")
#define CP_WAIT0()  asm volatile("cp.async.wait_group 0;" ::: "memory")

// ---------------- fused prep: zero cnt, B fp16 + bias, emb fp32->fp16 ----------------
#define CVT_GROUPS ((NU + NP) * 16)            // uint4 groups (8 halves)
#define CVT_BLOCKS ((CVT_GROUPS + 255) / 256)  // 18750
#define ZERO_INTS  (NALL + 64)
#define ZERO_BLOCKS ((ZERO_INTS + 1023) / 1024) // 587, 4 ints/thread
#define PREP_GRID (768 + CVT_BLOCKS + ZERO_BLOCKS)
__global__ void k_prep(const float* __restrict__ Wl, const float* __restrict__ bl,
                       const float* __restrict__ Wr,
                       const float* __restrict__ eu, const float* __restrict__ ep,
                       __half* __restrict__ Bh, float* __restrict__ Bias,
                       __half* __restrict__ xu16, __half* __restrict__ xp16,
                       int* __restrict__ cnt) {
    int b = blockIdx.x;
    if (b < 768) {
        int t = b / 192;
        int idx = (b % 192) * 256 + threadIdx.x;   // < 49152
        int layer = t >> 1, isU = t & 1;
        int rV = isU ? 1 : 0, rL = rV + 2;
        int n = idx / 384, k = idx % 384;
        const float* WlV = Wl + (size_t)((layer * 4 + rV) * 128) * 128;
        const float* WlL = Wl + (size_t)((layer * 4 + rL) * 128) * 128;
        const float* WrV = Wr + (size_t)((layer * 4 + rV) * 128) * 128;
        const float* WrL = Wr + (size_t)((layer * 4 + rL) * 128) * 128;
        float v;
        if (k < 128)      v = WlV[n * 128 + k];
        else if (k < 256) v = WlL[n * 128 + (k - 128)];
        else              v = WrV[n * 128 + (k - 256)] + WrL[n * 128 + (k - 256)];
        Bh[(size_t)t * 49152 + idx] = __float2half_rn(v);
        if (idx < 128)
            Bias[t * 128 + idx] = bl[(layer * 4 + rV) * 128 + idx] + bl[(layer * 4 + rL) * 128 + idx];
    } else if (b < 768 + CVT_BLOCKS) {
        long i = (long)(b - 768) * 256 + threadIdx.x;
        if (i >= CVT_GROUPS) return;
        const float* src; __half* dst; long j;
        if (i < (long)NU * 16) { src = eu; dst = xu16; j = i; }
        else                   { src = ep; dst = xp16; j = i - (long)NU * 16; }
        float4 a = __ldg(reinterpret_cast<const float4*>(src) + j * 2);
        float4 c = __ldg(reinterpret_cast<const float4*>(src) + j * 2 + 1);
        __half2 h0 = __floats2half2_rn(a.x, a.y);
        __half2 h1 = __floats2half2_rn(a.z, a.w);
        __half2 h2 = __floats2half2_rn(c.x, c.y);
        __half2 h3 = __floats2half2_rn(c.z, c.w);
        uint4 o;
        o.x = *reinterpret_cast<uint32_t*>(&h0);
        o.y = *reinterpret_cast<uint32_t*>(&h1);
        o.z = *reinterpret_cast<uint32_t*>(&h2);
        o.w = *reinterpret_cast<uint32_t*>(&h3);
        reinterpret_cast<uint4*>(dst)[j] = o;
    } else {
        long i = (long)(b - 768 - CVT_BLOCKS) * 1024 + threadIdx.x * 4;
        if (i + 3 < ZERO_INTS)
            *reinterpret_cast<int4*>(cnt + i) = make_int4(0, 0, 0, 0);
        else
            for (long q = i; q < ZERO_INTS; ++q) cnt[q] = 0;
    }
}

// ---------------- CSR build ----------------
__global__ void k_hist(const int* __restrict__ vs, const int* __restrict__ vd,
                       const int* __restrict__ ls, const int* __restrict__ ld,
                       int* __restrict__ cnt) {
    int i = blockIdx.x * blockDim.x + threadIdx.x;
    if (i < EV) { atomicAdd(&cnt[vd[i]], 1); atomicAdd(&cnt[2*NP + vs[i]], 1); }
    if (i < EL) { atomicAdd(&cnt[NP + ld[i]], 1); atomicAdd(&cnt[2*NP + NU + ls[i]], 1); }
}

__global__ void k_alloc(const int* __restrict__ cnt, int* __restrict__ offs,
                        int* __restrict__ cur, int* __restrict__ tot) {
    int w = blockIdx.x * blockDim.x + threadIdx.x;
    if (w >= NALL) return;
    int c = cnt[w];
    int base = c ? atomicAdd(tot, c) : 0;
    offs[w] = base;
    cur[w] = base;
}

__global__ void k_scatter(const int* __restrict__ vs, const int* __restrict__ vd,
                          const int* __restrict__ ls, const int* __restrict__ ld,
                          int* __restrict__ cur, int* __restrict__ pool) {
    int i = blockIdx.x * blockDim.x + threadIdx.x;
    if (i < EV) {
        int p = atomicAdd(&cur[vd[i]], 1);             pool[p] = vs[i];
        int q = atomicAdd(&cur[2*NP + vs[i]], 1);      pool[q] = vd[i];
    }
    if (i < EL) {
        int p = atomicAdd(&cur[NP + ld[i]], 1);        pool[p] = ls[i];
        int q = atomicAdd(&cur[2*NP + NU + ls[i]], 1); pool[q] = ld[i];
    }
}

// ---------------- CSR mean aggregation (fp16 tables, fp32 accum, fp16 out) ----------------
__global__ void agg_csr(const int* __restrict__ offs, const int* __restrict__ cnt,
                        const int* __restrict__ pool,
                        const __half* __restrict__ xu, const __half* __restrict__ xp,
                        __half* __restrict__ aVP, __half* __restrict__ aLP,
                        __half* __restrict__ aVU, __half* __restrict__ aLU) {
    int w = (blockIdx.x * blockDim.x + threadIdx.x) >> 5;
    int lane = threadIdx.x & 31;
    if (w >= NALL) return;
    const __half* X; __half* out;
    if (w < NP)                { X = xu; out = aVP + (size_t)w * H; }
    else if (w < 2*NP)         { X = xu; out = aLP + (size_t)(w - NP) * H; }
    else if (w < 2*NP + NU)    { X = xp; out = aVU + (size_t)(w - 2*NP) * H; }
    else                       { X = xp; out = aLU + (size_t)(w - 2*NP - NU) * H; }
    int beg = offs[w];
    int deg = cnt[w];
    int end = beg + deg;
    float4 acc0 = make_float4(0.f, 0.f, 0.f, 0.f);
    float4 acc1 = make_float4(0.f, 0.f, 0.f, 0.f);
    int i = beg;
    for (; i + 1 < end; i += 2) {
        int i0 = __ldg(pool + i);
        int i1 = __ldg(pool + i + 1);
        uint2 v0 = __ldg(reinterpret_cast<const uint2*>(X + (size_t)i0 * H) + lane);
        uint2 v1 = __ldg(reinterpret_cast<const uint2*>(X + (size_t)i1 * H) + lane);
        float2 a = __half22float2(*reinterpret_cast<__half2*>(&v0.x));
        float2 b = __half22float2(*reinterpret_cast<__half2*>(&v0.y));
        acc0.x += a.x; acc0.y += a.y; acc0.z += b.x; acc0.w += b.y;
        float2 c = __half22float2(*reinterpret_cast<__half2*>(&v1.x));
        float2 d = __half22float2(*reinterpret_cast<__half2*>(&v1.y));
        acc1.x += c.x; acc1.y += c.y; acc1.z += d.x; acc1.w += d.y;
    }
    if (i < end) {
        int i0 = __ldg(pool + i);
        uint2 v0 = __ldg(reinterpret_cast<const uint2*>(X + (size_t)i0 * H) + lane);
        float2 a = __half22float2(*reinterpret_cast<__half2*>(&v0.x));
        float2 b = __half22float2(*reinterpret_cast<__half2*>(&v0.y));
        acc0.x += a.x; acc0.y += a.y; acc0.z += b.x; acc0.w += b.y;
    }
    float inv = 1.0f / fmaxf((float)deg, 1.0f);
    __half2 r01 = __floats2half2_rn((acc0.x + acc1.x) * inv, (acc0.y + acc1.y) * inv);
    __half2 r23 = __floats2half2_rn((acc0.z + acc1.z) * inv, (acc0.w + acc1.w) * inv);
    uint2 o;
    o.x = *reinterpret_cast<uint32_t*>(&r01);
    o.y = *reinterpret_cast<uint32_t*>(&r23);
    reinterpret_cast<uint2*>(out)[lane] = o;
}

// ---------------- merged dual-type GEMM, cp.async double-buffered ----------------
// blocks [0,GP): posts; [GP,GP+GU): users.
// out[M,128] = [A0|A1|A2](M x 384 fp16) @ B^T + bias; fp32 accum.
#define RSTR 72
#define CHUNKB (128 * RSTR * 2)       // bytes per A or B buffer
#define GSMEM (4 * CHUNKB)            // 73728 B

template <bool OUTH>   // true: fp16 out + relu (layer 0); false: fp32 out (layer 1)
__global__ void __launch_bounds__(256, 2)
gemm_dual(const __half* __restrict__ pA0, const __half* __restrict__ pA1,
          const __half* __restrict__ pA2,
          const __half* __restrict__ uA0, const __half* __restrict__ uA1,
          const __half* __restrict__ uA2,
          const __half* __restrict__ BhP, const __half* __restrict__ BhU,
          const float* __restrict__ biasP, const float* __restrict__ biasU,
          void* __restrict__ outPv, void* __restrict__ outUv) {
    extern __shared__ __align__(16) __half sm[];
    const uint32_t sbase = smem_u32(sm);
    // layout: A buf0, A buf1, B buf0, B buf1
    const uint32_t uAb[2] = {sbase, sbase + CHUNKB};
    const uint32_t uBb[2] = {sbase + 2 * CHUNKB, sbase + 3 * CHUNKB};

    const bool isP = blockIdx.x < GP;
    const int row0 = (isP ? blockIdx.x : blockIdx.x - GP) << 7;
    const int M = isP ? NP : NU;
    const __half* A0 = isP ? pA0 : uA0;
    const __half* A1 = isP ? pA1 : uA1;
    const __half* A2 = isP ? pA2 : uA2;
    const __half* Bh = isP ? BhP : BhU;
    const float* bias = isP ? biasP : biasU;
    void* outv = isP ? outPv : outUv;

    const int tid = threadIdx.x;
    const int warp = tid >> 5, lane = tid & 31;
    const int wm = warp & 3, wn = warp >> 2;

    float acc[2][8][4];
#pragma unroll
    for (int i = 0; i < 2; ++i)
#pragma unroll
        for (int j = 0; j < 8; ++j)
#pragma unroll
            for (int q = 0; q < 4; ++q) acc[i][j][q] = 0.f;

    const int sr = tid >> 1;               // staging row 0..127
    const int shf = (tid & 1) << 5;        // k-half 0/32 (halves)
    const uint32_t soffB = (uint32_t)(sr * RSTR + shf) * 2;   // byte offset in buffer
    const int arow = row0 + sr;
    const int asz = (arow < M) ? 16 : 0;
    const int arowc = (arow < M) ? arow : row0;               // clamped valid address

    const int lA_row = lane & 15, lA_k = (lane >> 4) << 3;
    const int lB_row = ((lane >> 4) & 1) * 8 + (lane & 7);
    const int lB_k = ((lane >> 3) & 1) << 3;

    // ---- stage chunk c into buffer bi ----
    auto stage = [&](int c, int bi) {
        const __half* Asrc = (c < 2) ? A0 : (c < 4) ? A1 : A2;
        const int kb = (c & 1) << 6;
        const __half* ap = Asrc + (size_t)arowc * H + kb + shf;
        const __half* bp = Bh + (size_t)sr * 384 + c * 64 + shf;
#pragma unroll
        for (int q = 0; q < 4; ++q)
            cp16(uAb[bi] + soffB + q * 16, ap + q * 8, asz);
#pragma unroll
        for (int q = 0; q < 4; ++q)
            cp16(uBb[bi] + soffB + q * 16, bp + q * 8, 16);
    };

    stage(0, 0);
    CP_COMMIT();

#pragma unroll 1
    for (int c = 0; c < 6; ++c) {
        const int bi = c & 1;
        if (c < 5) {
            stage(c + 1, bi ^ 1);
            CP_COMMIT();
            CP_WAIT1();
        } else {
            CP_WAIT0();
        }
        __syncthreads();

#pragma unroll
        for (int ks = 0; ks < 4; ++ks) {
            uint32_t af[2][4];
#pragma unroll
            for (int mt = 0; mt < 2; ++mt) {
                uint32_t eo = ((wm * 32 + mt * 16 + lA_row) * RSTR + ks * 16 + lA_k) * 2;
                ldsm_x4(af[mt][0], af[mt][1], af[mt][2], af[mt][3], uAb[bi] + eo);
            }
            uint32_t bf[4][4];
#pragma unroll
            for (int np = 0; np < 4; ++np) {
                uint32_t eo = ((wn * 64 + np * 16 + lB_row) * RSTR + ks * 16 + lB_k) * 2;
                ldsm_x4(bf[np][0], bf[np][1], bf[np][2], bf[np][3], uBb[bi] + eo);
            }
#pragma unroll
            for (int mt = 0; mt < 2; ++mt)
#pragma unroll
                for (int nt = 0; nt < 8; ++nt)
                    mma_f16(acc[mt][nt], af[mt], &bf[nt >> 1][(nt & 1) << 1]);
        }
        __syncthreads();
    }

    // ---- epilogue ----
    const int lr = lane >> 2;
    const int lc = (lane & 3) << 1;
#pragma unroll
    for (int mt = 0; mt < 2; ++mt) {
        int r0 = row0 + wm * 32 + mt * 16 + lr;
#pragma unroll
        for (int nt = 0; nt < 8; ++nt) {
            int cn = wn * 64 + nt * 8 + lc;
            float b0 = __ldg(bias + cn), b1 = __ldg(bias + cn + 1);
            float* a4 = acc[mt][nt];
            if (OUTH) {
                __half* o16 = (__half*)outv;
                if (r0 < M) {
                    __half2 h = __floats2half2_rn(fmaxf(a4[0] + b0, 0.f), fmaxf(a4[1] + b1, 0.f));
                    *reinterpret_cast<__half2*>(o16 + (size_t)r0 * H + cn) = h;
                }
                if (r0 + 8 < M) {
                    __half2 h = __floats2half2_rn(fmaxf(a4[2] + b0, 0.f), fmaxf(a4[3] + b1, 0.f));
                    *reinterpret_cast<__half2*>(o16 + (size_t)(r0 + 8) * H + cn) = h;
                }
            } else {
                float* o32 = (float*)outv;
                if (r0 < M)
                    *reinterpret_cast<float2*>(o32 + (size_t)r0 * H + cn) =
                        make_float2(a4[0] + b0, a4[1] + b1);
                if (r0 + 8 < M)
                    *reinterpret_cast<float2*>(o32 + (size_t)(r0 + 8) * H + cn) =
                        make_float2(a4[2] + b0, a4[3] + b1);
            }
        }
    }
}

// ---------------- host ----------------
extern "C" void kernel_launch(void* const* d_in, const int* in_sizes, int n_in,
                              void* d_out, int out_size) {
    (void)in_sizes; (void)n_in; (void)out_size;
    const float* emb_u = (const float*)d_in[0];
    const float* emb_p = (const float*)d_in[1];
    const float* W_l   = (const float*)d_in[2];
    const float* b_l   = (const float*)d_in[3];
    const float* W_r   = (const float*)d_in[4];
    const int*   ev_s  = (const int*)d_in[5];
    const int*   ev_d  = (const int*)d_in[6];
    const int*   el_s  = (const int*)d_in[7];
    const int*   el_d  = (const int*)d_in[8];

    float* base = 0;
    cudaGetSymbolAddress((void**)&base, g_scratch);

    __half* aVP  = (__half*)(base + OFF_AVP);
    __half* aLP  = (__half*)(base + OFF_ALP);
    __half* aVU  = (__half*)(base + OFF_AVU);
    __half* aLU  = (__half*)(base + OFF_ALU);
    __half* xu0  = (__half*)(base + OFF_XU0);
    __half* xp0  = (__half*)(base + OFF_XP0);
    __half* xu1  = (__half*)(base + OFF_XU1);
    __half* xp1  = (__half*)(base + OFF_XP1);
    int*   ip  = (int*)(base + OFF_INT);
    int* cnt  = ip + I_CNT;
    int* tot  = ip + I_TOT;
    int* offs = ip + I_OFFS;
    int* cur  = ip + I_CUR;
    int* pool = ip + I_POOL;
    __half* Bh = (__half*)(base + OFF_BH);
    float* Bias = base + OFF_BIAS;

    float* outU = (float*)d_out;
    float* outP = outU + (size_t)NU * H;

    cudaFuncSetAttribute(gemm_dual<true>,  cudaFuncAttributeMaxDynamicSharedMemorySize, GSMEM);
    cudaFuncSetAttribute(gemm_dual<false>, cudaFuncAttributeMaxDynamicSharedMemorySize, GSMEM);

    // launch 1: prep (zero cnt + B fp16 + emb cvt)
    k_prep<<<PREP_GRID, 256>>>(W_l, b_l, W_r, emb_u, emb_p, Bh, Bias, xu0, xp0, cnt);
    // launches 2-4: CSR build
    k_hist<<<(EV + 255) / 256, 256>>>(ev_s, ev_d, el_s, el_d, cnt);
    k_alloc<<<(NALL + 255) / 256, 256>>>(cnt, offs, cur, tot);
    k_scatter<<<(EV + 255) / 256, 256>>>(ev_s, ev_d, el_s, el_d, cur, pool);

    const int AGG_BLOCKS = NALL / 8;

    // ---- layer 0 (launch 5 = agg_csr -> profiled slot) ----
    agg_csr<<<AGG_BLOCKS, 256>>>(offs, cnt, pool, xu0, xp0, aVP, aLP, aVU, aLU);
    gemm_dual<true><<<GP + GU, 256, GSMEM>>>(aVP, aLP, xp0, aVU, aLU, xu0,
                                             Bh + 0 * 49152, Bh + 1 * 49152,
                                             Bias + 0 * 128, Bias + 1 * 128,
                                             xp1, xu1);
    // ---- layer 1 ----
    agg_csr<<<AGG_BLOCKS, 256>>>(offs, cnt, pool, xu1, xp1, aVP, aLP, aVU, aLU);
    gemm_dual<false><<<GP + GU, 256, GSMEM>>>(aVP, aLP, xp1, aVU, aLU, xu1,
                                              Bh + 2 * 49152, Bh + 3 * 49152,
                                              Bias + 2 * 128, Bias + 3 * 128,
                                              outP, outU);
}